// round 2
// baseline (speedup 1.0000x reference)
#include <cuda_runtime.h>
#include <math.h>

#define MAXN 50048
#define MAXE 600064

// ---------------- scratch (static device globals; no allocation) ----------------
__device__ float g_b1[(size_t)MAXN * 128];   // hn -> attn (reused)
__device__ float g_Q [(size_t)MAXN * 128];   // Q -> y (reused)
__device__ float g_K [(size_t)MAXN * 128];   // K -> nf (reused)
__device__ float g_V [(size_t)MAXN * 128];
__device__ float g_x [(size_t)MAXN * 128];
__device__ float g_wV[(size_t)MAXN * 128];
__device__ float g_z [(size_t)MAXN * 4];
__device__ float g_t [(size_t)MAXN * 256];
__device__ float g_en[(size_t)MAXN];

__device__ __forceinline__ float clip5(float x) { return fminf(fmaxf(x, -5.f), 5.f); }
__device__ __forceinline__ float sigm(float x)  { return 1.f / (1.f + expf(-x)); }

// ---------------- zero fill ----------------
__global__ void fzero_kernel(float4* __restrict__ p, int n4) {
    int i = blockIdx.x * blockDim.x + threadIdx.x;
    if (i < n4) p[i] = make_float4(0.f, 0.f, 0.f, 0.f);
}

// ---------------- row LayerNorm (warp per 128-wide row) ----------------
__global__ void ln_kernel(const float* __restrict__ in, float* __restrict__ out,
                          const float* __restrict__ w, const float* __restrict__ b, int rows) {
    int warp = (blockIdx.x * blockDim.x + threadIdx.x) >> 5;
    int lane = threadIdx.x & 31;
    if (warp >= rows) return;
    float4 v = *(const float4*)(in + (size_t)warp * 128 + 4 * lane);
    float s  = v.x + v.y + v.z + v.w;
    float sq = v.x * v.x + v.y * v.y + v.z * v.z + v.w * v.w;
#pragma unroll
    for (int o = 16; o; o >>= 1) {
        s  += __shfl_xor_sync(0xffffffffu, s,  o);
        sq += __shfl_xor_sync(0xffffffffu, sq, o);
    }
    float mu   = s * (1.f / 128.f);
    float rstd = rsqrtf(sq * (1.f / 128.f) - mu * mu + 1e-5f);
    float4 wv = *(const float4*)(w + 4 * lane);
    float4 bv = *(const float4*)(b + 4 * lane);
    float4 o4;
    o4.x = (v.x - mu) * rstd * wv.x + bv.x;
    o4.y = (v.y - mu) * rstd * wv.y + bv.y;
    o4.z = (v.z - mu) * rstd * wv.z + bv.z;
    o4.w = (v.w - mu) * rstd * wv.w + bv.w;
    *(float4*)(out + (size_t)warp * 128 + 4 * lane) = o4;
}

// ---------------- generic GEMM: C[M,NC] = A[M,K] @ W[K,NC], tile 64x128, BK=32 ----------
// EPI: 0 none, 1 += bias[c] + res[r,c], 2 SiLU, 3 += res[r,c]
template <int EPI>
__global__ void __launch_bounds__(256) gemm_kernel(
    const float* __restrict__ A, const float* __restrict__ W,
    const float* __restrict__ bias, const float* __restrict__ res,
    float* __restrict__ C, int M, int K, int NC) {
    __shared__ float A_sh[64 * 36];
    __shared__ float W_sh[32 * 132];
    int tid = threadIdx.x;
    int ty = tid >> 4, tx = tid & 15;
    int row0 = blockIdx.x * 64;
    int cb   = blockIdx.y * 128;
    float acc[4][8];
#pragma unroll
    for (int i = 0; i < 4; i++)
#pragma unroll
        for (int u = 0; u < 8; u++) acc[i][u] = 0.f;

    int nkt = K >> 5;
    for (int kt = 0; kt < nkt; ++kt) {
#pragma unroll
        for (int it = 0; it < 2; ++it) {   // A tile: 64x32
            int idx = tid + it * 256;
            int r = idx >> 3, c4 = (idx & 7) << 2;
            float4 v = make_float4(0.f, 0.f, 0.f, 0.f);
            if (row0 + r < M) v = *(const float4*)(A + (size_t)(row0 + r) * K + kt * 32 + c4);
            *(float4*)(A_sh + r * 36 + c4) = v;
        }
#pragma unroll
        for (int it = 0; it < 4; ++it) {   // W tile: 32x128
            int idx = tid + it * 256;
            int kk = idx >> 5, c4 = (idx & 31) << 2;
            *(float4*)(W_sh + kk * 132 + c4) =
                *(const float4*)(W + (size_t)(kt * 32 + kk) * NC + cb + c4);
        }
        __syncthreads();
#pragma unroll
        for (int kk = 0; kk < 32; ++kk) {
            float a[4];
#pragma unroll
            for (int i = 0; i < 4; i++) a[i] = A_sh[(4 * ty + i) * 36 + kk];
            float wv[8];
            *(float4*)&wv[0] = *(float4*)(W_sh + kk * 132 + 8 * tx);
            *(float4*)&wv[4] = *(float4*)(W_sh + kk * 132 + 8 * tx + 4);
#pragma unroll
            for (int i = 0; i < 4; i++)
#pragma unroll
                for (int u = 0; u < 8; u++) acc[i][u] += a[i] * wv[u];
        }
        __syncthreads();
    }
#pragma unroll
    for (int i = 0; i < 4; i++) {
        int r = row0 + 4 * ty + i;
        if (r >= M) continue;
#pragma unroll
        for (int u = 0; u < 8; u++) {
            int c = cb + 8 * tx + u;
            float v = acc[i][u];
            if (EPI == 1) v += bias[c] + res[(size_t)r * NC + c];
            if (EPI == 2) v = v * (1.f / (1.f + expf(-v)));
            if (EPI == 3) v += res[(size_t)r * NC + c];
            C[(size_t)r * NC + c] = v;
        }
    }
}

// ---------------- fused edge kernel: LN(edge) -> Pe GEMM -> score/exp -> atomic scatter ----
__global__ void __launch_bounds__(256) edge_kernel(
    const float* __restrict__ ef, const float* __restrict__ lnw, const float* __restrict__ lnb,
    const float* __restrict__ We, const int* __restrict__ src, const int* __restrict__ dst,
    const float* __restrict__ Q, const float* __restrict__ Kv, const float* __restrict__ V,
    float* __restrict__ wV, float* __restrict__ z, int E) {
    extern __shared__ float sh[];
    float* LN_sh = sh;                   // [64][132] ln rows, later Pe
    float* W_sh  = sh + 64 * 132;        // [32][132]
    int* s_sh = (int*)(W_sh + 32 * 132); // [64]
    int* d_sh = s_sh + 64;               // [64]

    int tid = threadIdx.x, lane = tid & 31, w = tid >> 5;
    int e0 = blockIdx.x * 64;
    if (tid < 64) {
        int e = e0 + tid;
        s_sh[tid] = (e < E) ? src[e] : 0;
        d_sh[tid] = (e < E) ? dst[e] : 0;
    }
    float4 lw = *(const float4*)(lnw + 4 * lane);
    float4 lb = *(const float4*)(lnb + 4 * lane);
    // phase A: LN of 8 edge rows per warp
#pragma unroll
    for (int i = 0; i < 8; i++) {
        int r = w * 8 + i;
        int e = e0 + r;
        float4 v = make_float4(0.f, 0.f, 0.f, 0.f);
        if (e < E) v = *(const float4*)(ef + (size_t)e * 128 + 4 * lane);
        float s  = v.x + v.y + v.z + v.w;
        float sq = v.x * v.x + v.y * v.y + v.z * v.z + v.w * v.w;
#pragma unroll
        for (int o = 16; o; o >>= 1) {
            s  += __shfl_xor_sync(0xffffffffu, s,  o);
            sq += __shfl_xor_sync(0xffffffffu, sq, o);
        }
        float mu   = s * (1.f / 128.f);
        float rstd = rsqrtf(sq * (1.f / 128.f) - mu * mu + 1e-5f);
        float4 o4;
        o4.x = (v.x - mu) * rstd * lw.x + lb.x;
        o4.y = (v.y - mu) * rstd * lw.y + lb.y;
        o4.z = (v.z - mu) * rstd * lw.z + lb.z;
        o4.w = (v.w - mu) * rstd * lw.w + lb.w;
        *(float4*)(LN_sh + r * 132 + 4 * lane) = o4;
    }
    __syncthreads();
    // phase B: Pe[64][128] = LN @ We
    int ty = tid >> 4, tx = tid & 15;
    float acc[4][8];
#pragma unroll
    for (int i = 0; i < 4; i++)
#pragma unroll
        for (int u = 0; u < 8; u++) acc[i][u] = 0.f;
    for (int kt = 0; kt < 4; ++kt) {
#pragma unroll
        for (int it = 0; it < 4; ++it) {
            int idx = tid + it * 256;
            int kk = idx >> 5, c4 = (idx & 31) << 2;
            *(float4*)(W_sh + kk * 132 + c4) =
                *(const float4*)(We + (size_t)(kt * 32 + kk) * 128 + c4);
        }
        __syncthreads();
#pragma unroll
        for (int kk = 0; kk < 32; ++kk) {
            int k = kt * 32 + kk;
            float a[4];
#pragma unroll
            for (int i = 0; i < 4; i++) a[i] = LN_sh[(4 * ty + i) * 132 + k];
            float wv[8];
            *(float4*)&wv[0] = *(float4*)(W_sh + kk * 132 + 8 * tx);
            *(float4*)&wv[4] = *(float4*)(W_sh + kk * 132 + 8 * tx + 4);
#pragma unroll
            for (int i = 0; i < 4; i++)
#pragma unroll
                for (int u = 0; u < 8; u++) acc[i][u] += a[i] * wv[u];
        }
        __syncthreads();
    }
    // stash Pe into LN_sh (LN values dead now)
#pragma unroll
    for (int i = 0; i < 4; i++) {
        *(float4*)(LN_sh + (4 * ty + i) * 132 + 8 * tx)     = *(float4*)&acc[i][0];
        *(float4*)(LN_sh + (4 * ty + i) * 132 + 8 * tx + 4) = *(float4*)&acc[i][4];
    }
    __syncthreads();
    // phase C: per-edge score, exp, scatter
    const float inv = 0.17677669529663687f;  // 1/sqrt(32)
    int head = lane >> 3;
#pragma unroll
    for (int j = 0; j < 8; j++) {
        int r = w * 8 + j;
        int e = e0 + r;
        if (e >= E) break;
        int si = s_sh[r], di = d_sh[r];
        float4 kq = *(const float4*)(Kv + (size_t)si * 128 + 4 * lane);
        float4 qv = *(const float4*)(Q  + (size_t)di * 128 + 4 * lane);
        float4 pe = *(float4*)(LN_sh + r * 132 + 4 * lane);
        float t = clip5(kq.x * qv.x * inv) * pe.x + clip5(kq.y * qv.y * inv) * pe.y
                + clip5(kq.z * qv.z * inv) * pe.z + clip5(kq.w * qv.w * inv) * pe.w;
        t += __shfl_xor_sync(0xffffffffu, t, 1);
        t += __shfl_xor_sync(0xffffffffu, t, 2);
        t += __shfl_xor_sync(0xffffffffu, t, 4);
        float s = expf(clip5(t));
        float4 vv = *(const float4*)(V + (size_t)si * 128 + 4 * lane);
        float* dp = wV + (size_t)di * 128 + 4 * lane;
        atomicAdd(dp + 0, vv.x * s);
        atomicAdd(dp + 1, vv.y * s);
        atomicAdd(dp + 2, vv.z * s);
        atomicAdd(dp + 3, vv.w * s);
        if ((lane & 7) == 0) atomicAdd(z + (size_t)di * 4 + head, s);
    }
}

// ---------------- attn = wV / (z + 1e-6) ----------------
__global__ void attn_kernel(const float* __restrict__ wV, const float* __restrict__ z,
                            float* __restrict__ outp, int N) {
    int i = blockIdx.x * blockDim.x + threadIdx.x;  // over N*32 float4s
    if (i >= N * 32) return;
    int n = i >> 5;
    int head = (i & 31) >> 3;
    float invz = 1.f / (z[(size_t)n * 4 + head] + 1e-6f);
    float4 v = *(const float4*)(wV + (size_t)i * 4);
    v.x *= invz; v.y *= invz; v.z *= invz; v.w *= invz;
    *(float4*)(outp + (size_t)i * 4) = v;
}

// ---------------- Set2Set: one block per graph, all 3 iterations internal ----------------
__global__ void __launch_bounds__(256) set2set_kernel(
    const float* __restrict__ nf, const int* __restrict__ gid,
    const float* __restrict__ W_ih, const float* __restrict__ W_hh,
    const float* __restrict__ b_ih, const float* __restrict__ b_hh,
    float* __restrict__ ener, float* __restrict__ out, int N) {
    __shared__ float qs[256], hh[128], cc[128], gates[512], rsh[8 * 128], red[16];
    int tid = threadIdx.x, lane = tid & 31, w = tid >> 5;
    int g = blockIdx.x;
    // node range of this graph (gid sorted ascending)
    int lo, hi;
    {
        int a = 0, b = N;
        while (a < b) { int m = (a + b) >> 1; if (gid[m] < g) a = m + 1; else b = m; }
        lo = a;
        b = N;
        while (a < b) { int m = (a + b) >> 1; if (gid[m] < g + 1) a = m + 1; else b = m; }
        hi = a;
    }
    qs[tid] = 0.f;
    if (tid < 128) { hh[tid] = 0.f; cc[tid] = 0.f; }
    __syncthreads();

    for (int it = 0; it < 3; ++it) {
        // LSTM gates
        for (int j = tid; j < 512; j += 256) {
            float acc = b_ih[j] + b_hh[j];
            const float* wi = W_ih + (size_t)j * 256;
#pragma unroll 8
            for (int k2 = 0; k2 < 256; k2++) acc += qs[k2] * wi[k2];
            const float* whp = W_hh + (size_t)j * 128;
#pragma unroll 8
            for (int k2 = 0; k2 < 128; k2++) acc += hh[k2] * whp[k2];
            gates[j] = acc;
        }
        __syncthreads();
        if (tid < 128) {
            float c = sigm(gates[128 + tid]) * cc[tid] + sigm(gates[tid]) * tanhf(gates[256 + tid]);
            cc[tid] = c;
            hh[tid] = sigm(gates[384 + tid]) * tanhf(c);
        }
        __syncthreads();
        // pass 1: energies + max
        float mloc = -INFINITY;
        float4 h4 = *(float4*)&hh[4 * lane];
        for (int n = lo + w; n < hi; n += 8) {
            float4 a4 = *(const float4*)(nf + (size_t)n * 128 + 4 * lane);
            float t = a4.x * h4.x + a4.y * h4.y + a4.z * h4.z + a4.w * h4.w;
#pragma unroll
            for (int o = 16; o; o >>= 1) t += __shfl_xor_sync(0xffffffffu, t, o);
            if (lane == 0) ener[n] = t;
            mloc = fmaxf(mloc, t);
        }
#pragma unroll
        for (int o = 16; o; o >>= 1) mloc = fmaxf(mloc, __shfl_xor_sync(0xffffffffu, mloc, o));
        if (lane == 0) red[w] = mloc;
        __syncthreads();
        if (tid == 0) {
            float m = -INFINITY;
            for (int i = 0; i < 8; i++) m = fmaxf(m, red[i]);
            red[8] = m;
        }
        __syncthreads();
        float m = red[8];
        // pass 2: denom
        float dloc = 0.f;
        for (int n = lo + tid; n < hi; n += 256) dloc += expf(ener[n] - m);
#pragma unroll
        for (int o = 16; o; o >>= 1) dloc += __shfl_xor_sync(0xffffffffu, dloc, o);
        __syncthreads();
        if (lane == 0) red[w] = dloc;
        __syncthreads();
        if (tid == 0) {
            float d = 0.f;
            for (int i = 0; i < 8; i++) d += red[i];
            red[9] = d;
        }
        __syncthreads();
        float invd = 1.f / red[9];
        // pass 3: readout
        float4 racc = make_float4(0.f, 0.f, 0.f, 0.f);
        for (int n = lo + w; n < hi; n += 8) {
            float coef = expf(ener[n] - m) * invd;
            float4 a4 = *(const float4*)(nf + (size_t)n * 128 + 4 * lane);
            racc.x += coef * a4.x; racc.y += coef * a4.y;
            racc.z += coef * a4.z; racc.w += coef * a4.w;
        }
        *(float4*)&rsh[w * 128 + 4 * lane] = racc;
        __syncthreads();
        if (tid < 128) {
            float ro = 0.f;
#pragma unroll
            for (int i = 0; i < 8; i++) ro += rsh[i * 128 + tid];
            qs[tid] = hh[tid];
            qs[128 + tid] = ro;
        }
        __syncthreads();
    }
    out[(size_t)g * 256 + tid] = qs[tid];
}

// ---------------- launch ----------------
extern "C" void kernel_launch(void* const* d_in, const int* in_sizes, int n_in,
                              void* d_out, int out_size) {
    const float* node = (const float*)d_in[0];
    const float* edge = (const float*)d_in[1];
    const float* Wq = (const float*)d_in[2];
    const float* Wk = (const float*)d_in[3];
    const float* Wv = (const float*)d_in[4];
    const float* We = (const float*)d_in[5];
    const float* Wo = (const float*)d_in[6];
    const float* bo = (const float*)d_in[7];
    const float* W1 = (const float*)d_in[8];
    const float* W2 = (const float*)d_in[9];
    const float* l1nw = (const float*)d_in[10];
    const float* l1nb = (const float*)d_in[11];
    const float* l1ew = (const float*)d_in[12];
    const float* l1eb = (const float*)d_in[13];
    const float* l2w = (const float*)d_in[14];
    const float* l2b = (const float*)d_in[15];
    const float* Wih = (const float*)d_in[16];
    const float* Whh = (const float*)d_in[17];
    const float* bih = (const float*)d_in[18];
    const float* bhh = (const float*)d_in[19];
    const int* src = (const int*)d_in[20];
    const int* dst = (const int*)d_in[21];
    const int* gid = (const int*)d_in[22];

    int N = in_sizes[0] / 128;
    int E = in_sizes[20];
    int G = out_size / 256;

    float *b1, *q, *k, *v, *x, *wv, *z, *t, *en;
    cudaGetSymbolAddress((void**)&b1, g_b1);
    cudaGetSymbolAddress((void**)&q,  g_Q);
    cudaGetSymbolAddress((void**)&k,  g_K);
    cudaGetSymbolAddress((void**)&v,  g_V);
    cudaGetSymbolAddress((void**)&x,  g_x);
    cudaGetSymbolAddress((void**)&wv, g_wV);
    cudaGetSymbolAddress((void**)&z,  g_z);
    cudaGetSymbolAddress((void**)&t,  g_t);
    cudaGetSymbolAddress((void**)&en, g_en);

    const int edge_smem = (64 * 132 + 32 * 132) * 4 + 128 * 4;
    cudaFuncSetAttribute(edge_kernel, cudaFuncAttributeMaxDynamicSharedMemorySize, edge_smem);

    int gnodes = (N + 63) / 64;

    // 1) LN(node) -> b1
    ln_kernel<<<(N + 7) / 8, 256>>>(node, b1, l1nw, l1nb, N);
    // 2) Q, K, V
    gemm_kernel<0><<<dim3(gnodes, 1), 256>>>(b1, Wq, nullptr, nullptr, q, N, 128, 128);
    gemm_kernel<0><<<dim3(gnodes, 1), 256>>>(b1, Wk, nullptr, nullptr, k, N, 128, 128);
    gemm_kernel<0><<<dim3(gnodes, 1), 256>>>(b1, Wv, nullptr, nullptr, v, N, 128, 128);
    // 3) zero accumulators
    fzero_kernel<<<(N * 32 + 255) / 256, 256>>>((float4*)wv, N * 32);
    fzero_kernel<<<(N + 255) / 256, 256>>>((float4*)z, N);
    // 4) fused edge kernel
    edge_kernel<<<(E + 63) / 64, 256, edge_smem>>>(edge, l1ew, l1eb, We, src, dst,
                                                   q, k, v, wv, z, E);
    // 5) attn -> b1
    attn_kernel<<<(N * 32 + 255) / 256, 256>>>(wv, z, b1, N);
    // 6) x = node + attn@Wo + bo
    gemm_kernel<1><<<dim3(gnodes, 1), 256>>>(b1, Wo, bo, node, x, N, 128, 128);
    // 7) y = LN2(x) -> q (reuse)
    ln_kernel<<<(N + 7) / 8, 256>>>(x, q, l2w, l2b, N);
    // 8) t = silu(y @ W1)   [N,256]
    gemm_kernel<2><<<dim3(gnodes, 2), 256>>>(q, W1, nullptr, nullptr, t, N, 128, 256);
    // 9) nf = x + t @ W2 -> k (reuse)
    gemm_kernel<3><<<dim3(gnodes, 1), 256>>>(t, W2, nullptr, x, k, N, 256, 128);
    // 10) Set2Set readout (3 iterations inside)
    set2set_kernel<<<G, 256>>>(k, gid, Wih, Whh, bih, bhh, en, (float*)d_out, N);
}

// round 3
// speedup vs baseline: 1.3579x; 1.3579x over previous
#include <cuda_runtime.h>
#include <math.h>

#define MAXN 50048
#define MAXE 600064

// ---------------- scratch (static device globals; no allocation) ----------------
__device__ float g_b1[(size_t)MAXN * 128];   // hn -> attn (reused)
__device__ float g_Q [(size_t)MAXN * 128];   // Q -> y (reused)
__device__ float g_K [(size_t)MAXN * 128];   // K -> nf (reused)
__device__ float g_V [(size_t)MAXN * 128];
__device__ float g_x [(size_t)MAXN * 128];
__device__ float g_wV[(size_t)MAXN * 128];
__device__ float g_z [(size_t)MAXN * 4];
__device__ float g_t [(size_t)MAXN * 256];
__device__ float g_en[(size_t)MAXN];

__device__ __forceinline__ float clip5(float x) { return fminf(fmaxf(x, -5.f), 5.f); }
__device__ __forceinline__ float sigm(float x)  { return 1.f / (1.f + expf(-x)); }

// ---- packed f32x2 helpers (FFMA2: 2 MACs per issue slot; fp32-exact) ----
typedef unsigned long long u64t;
__device__ __forceinline__ u64t pack2(float x) {
    u64t r; asm("mov.b64 %0, {%1, %1};" : "=l"(r) : "f"(x)); return r;
}
__device__ __forceinline__ void ffma2(u64t& d, u64t a, u64t b) {
    asm("fma.rn.f32x2 %0, %1, %2, %0;" : "+l"(d) : "l"(a), "l"(b));
}
__device__ __forceinline__ float2 unpack2(u64t v) {
    float2 r; asm("mov.b64 {%0, %1}, %2;" : "=f"(r.x), "=f"(r.y) : "l"(v)); return r;
}
__device__ __forceinline__ void red_add_v4(float* p, float a, float b, float c, float d) {
    asm volatile("red.global.add.v4.f32 [%0], {%1,%2,%3,%4};"
                 :: "l"(p), "f"(a), "f"(b), "f"(c), "f"(d) : "memory");
}

// ---------------- zero fill ----------------
__global__ void fzero_kernel(float4* __restrict__ p, int n4) {
    int i = blockIdx.x * blockDim.x + threadIdx.x;
    if (i < n4) p[i] = make_float4(0.f, 0.f, 0.f, 0.f);
}

// ---------------- row LayerNorm (warp per 128-wide row) ----------------
__global__ void ln_kernel(const float* __restrict__ in, float* __restrict__ out,
                          const float* __restrict__ w, const float* __restrict__ b, int rows) {
    int warp = (blockIdx.x * blockDim.x + threadIdx.x) >> 5;
    int lane = threadIdx.x & 31;
    if (warp >= rows) return;
    float4 v = *(const float4*)(in + (size_t)warp * 128 + 4 * lane);
    float s  = v.x + v.y + v.z + v.w;
    float sq = v.x * v.x + v.y * v.y + v.z * v.z + v.w * v.w;
#pragma unroll
    for (int o = 16; o; o >>= 1) {
        s  += __shfl_xor_sync(0xffffffffu, s,  o);
        sq += __shfl_xor_sync(0xffffffffu, sq, o);
    }
    float mu   = s * (1.f / 128.f);
    float rstd = rsqrtf(sq * (1.f / 128.f) - mu * mu + 1e-5f);
    float4 wv = *(const float4*)(w + 4 * lane);
    float4 bv = *(const float4*)(b + 4 * lane);
    float4 o4;
    o4.x = (v.x - mu) * rstd * wv.x + bv.x;
    o4.y = (v.y - mu) * rstd * wv.y + bv.y;
    o4.z = (v.z - mu) * rstd * wv.z + bv.z;
    o4.w = (v.w - mu) * rstd * wv.w + bv.w;
    *(float4*)(out + (size_t)warp * 128 + 4 * lane) = o4;
}

// ---------------- GEMM body: C[M,NC] tile 128x128, BK=32, 8x8/thread, FFMA2 -------------
// EPI: 0 none, 1 += bias[c] + res[r,c], 2 SiLU, 3 += res[r,c]
template <int EPI>
__device__ __forceinline__ void gemm_body(
    const float* __restrict__ A, const float* __restrict__ W,
    const float* __restrict__ bias, const float* __restrict__ res,
    float* __restrict__ C, int M, int K, int NC, int row0, int cb,
    float* A_sh /*128*37*/, float* W_sh /*32*132*/) {
    int tid = threadIdx.x;
    int ty = tid >> 4, tx = tid & 15;
    u64t acc[8][4];
#pragma unroll
    for (int i = 0; i < 8; i++)
#pragma unroll
        for (int u = 0; u < 4; u++) acc[i][u] = 0ull;

    int nkt = K >> 5;
    for (int kt = 0; kt < nkt; ++kt) {
#pragma unroll
        for (int it = 0; it < 4; ++it) {   // A tile: 128x32
            int idx = tid + it * 256;
            int r = idx >> 3, c4 = (idx & 7) << 2;
            float4 v = make_float4(0.f, 0.f, 0.f, 0.f);
            if (row0 + r < M) v = *(const float4*)(A + (size_t)(row0 + r) * K + kt * 32 + c4);
            A_sh[r * 37 + c4 + 0] = v.x;
            A_sh[r * 37 + c4 + 1] = v.y;
            A_sh[r * 37 + c4 + 2] = v.z;
            A_sh[r * 37 + c4 + 3] = v.w;
        }
#pragma unroll
        for (int it = 0; it < 4; ++it) {   // W tile: 32x128
            int idx = tid + it * 256;
            int kk = idx >> 5, c4 = (idx & 31) << 2;
            *(float4*)(W_sh + kk * 132 + c4) =
                *(const float4*)(W + (size_t)(kt * 32 + kk) * NC + cb + c4);
        }
        __syncthreads();
#pragma unroll
        for (int kk = 0; kk < 32; ++kk) {
            u64t w2[4];
            {
                const ulonglong2* wp = (const ulonglong2*)(W_sh + kk * 132 + 8 * tx);
                ulonglong2 w01 = wp[0];
                ulonglong2 w23 = wp[1];
                w2[0] = w01.x; w2[1] = w01.y; w2[2] = w23.x; w2[3] = w23.y;
            }
#pragma unroll
            for (int i = 0; i < 8; i++) {
                u64t a2 = pack2(A_sh[(8 * ty + i) * 37 + kk]);
                ffma2(acc[i][0], a2, w2[0]);
                ffma2(acc[i][1], a2, w2[1]);
                ffma2(acc[i][2], a2, w2[2]);
                ffma2(acc[i][3], a2, w2[3]);
            }
        }
        __syncthreads();
    }
    // epilogue
#pragma unroll
    for (int i = 0; i < 8; i++) {
        int r = row0 + 8 * ty + i;
        if (r >= M) continue;
        float o[8];
        float2 p0 = unpack2(acc[i][0]), p1 = unpack2(acc[i][1]);
        float2 p2 = unpack2(acc[i][2]), p3 = unpack2(acc[i][3]);
        o[0] = p0.x; o[1] = p0.y; o[2] = p1.x; o[3] = p1.y;
        o[4] = p2.x; o[5] = p2.y; o[6] = p3.x; o[7] = p3.y;
        int cbase = cb + 8 * tx;
        if (EPI == 1) {
            float4 b0 = *(const float4*)(bias + cbase);
            float4 b1 = *(const float4*)(bias + cbase + 4);
            float4 r0 = *(const float4*)(res + (size_t)r * NC + cbase);
            float4 r1 = *(const float4*)(res + (size_t)r * NC + cbase + 4);
            o[0] += b0.x + r0.x; o[1] += b0.y + r0.y; o[2] += b0.z + r0.z; o[3] += b0.w + r0.w;
            o[4] += b1.x + r1.x; o[5] += b1.y + r1.y; o[6] += b1.z + r1.z; o[7] += b1.w + r1.w;
        }
        if (EPI == 2) {
#pragma unroll
            for (int u = 0; u < 8; u++) o[u] = o[u] / (1.f + expf(-o[u]));
        }
        if (EPI == 3) {
            float4 r0 = *(const float4*)(res + (size_t)r * NC + cbase);
            float4 r1 = *(const float4*)(res + (size_t)r * NC + cbase + 4);
            o[0] += r0.x; o[1] += r0.y; o[2] += r0.z; o[3] += r0.w;
            o[4] += r1.x; o[5] += r1.y; o[6] += r1.z; o[7] += r1.w;
        }
        *(float4*)(C + (size_t)r * NC + cbase)     = make_float4(o[0], o[1], o[2], o[3]);
        *(float4*)(C + (size_t)r * NC + cbase + 4) = make_float4(o[4], o[5], o[6], o[7]);
    }
}

template <int EPI>
__global__ void __launch_bounds__(256, 2) gemm_kernel(
    const float* __restrict__ A, const float* __restrict__ W,
    const float* __restrict__ bias, const float* __restrict__ res,
    float* __restrict__ C, int M, int K, int NC) {
    __shared__ float A_sh[128 * 37];
    __shared__ float W_sh[32 * 132];
    gemm_body<EPI>(A, W, bias, res, C, M, K, NC, blockIdx.x * 128, blockIdx.y * 128, A_sh, W_sh);
}

// fused Q/K/V: grid.y selects the weight + output
__global__ void __launch_bounds__(256, 2) qkv_kernel(
    const float* __restrict__ A,
    const float* __restrict__ Wq, const float* __restrict__ Wk, const float* __restrict__ Wv,
    float* __restrict__ Q, float* __restrict__ Ko, float* __restrict__ V, int M) {
    __shared__ float A_sh[128 * 37];
    __shared__ float W_sh[32 * 132];
    const float* W = (blockIdx.y == 0) ? Wq : (blockIdx.y == 1) ? Wk : Wv;
    float* C       = (blockIdx.y == 0) ? Q  : (blockIdx.y == 1) ? Ko : V;
    gemm_body<0>(A, W, nullptr, nullptr, C, M, 128, 128, blockIdx.x * 128, 0, A_sh, W_sh);
}

// ---------------- fused edge kernel: LN(edge) -> Pe GEMM -> score/exp -> scatter --------
// tile = 128 edges
__global__ void __launch_bounds__(256, 2) edge_kernel(
    const float* __restrict__ ef, const float* __restrict__ lnw, const float* __restrict__ lnb,
    const float* __restrict__ We, const int* __restrict__ src, const int* __restrict__ dst,
    const float* __restrict__ Q, const float* __restrict__ Kv, const float* __restrict__ V,
    float* __restrict__ wV, float* __restrict__ z, int E) {
    extern __shared__ float sh[];
    float* LN_sh = sh;                    // [128][132] ln rows, later Pe
    float* W_sh  = sh + 128 * 132;        // [32][132]
    int* s_sh = (int*)(W_sh + 32 * 132);  // [128]
    int* d_sh = s_sh + 128;               // [128]

    int tid = threadIdx.x, lane = tid & 31, w = tid >> 5;
    int e0 = blockIdx.x * 128;
    if (tid < 128) {
        int e = e0 + tid;
        s_sh[tid] = (e < E) ? src[e] : 0;
        d_sh[tid] = (e < E) ? dst[e] : 0;
    }
    float4 lw = *(const float4*)(lnw + 4 * lane);
    float4 lb = *(const float4*)(lnb + 4 * lane);
    // phase A: LN of 16 edge rows per warp
#pragma unroll
    for (int i = 0; i < 16; i++) {
        int r = w * 16 + i;
        int e = e0 + r;
        float4 v = make_float4(0.f, 0.f, 0.f, 0.f);
        if (e < E) v = *(const float4*)(ef + (size_t)e * 128 + 4 * lane);
        float s  = v.x + v.y + v.z + v.w;
        float sq = v.x * v.x + v.y * v.y + v.z * v.z + v.w * v.w;
#pragma unroll
        for (int o = 16; o; o >>= 1) {
            s  += __shfl_xor_sync(0xffffffffu, s,  o);
            sq += __shfl_xor_sync(0xffffffffu, sq, o);
        }
        float mu   = s * (1.f / 128.f);
        float rstd = rsqrtf(sq * (1.f / 128.f) - mu * mu + 1e-5f);
        float4 o4;
        o4.x = (v.x - mu) * rstd * lw.x + lb.x;
        o4.y = (v.y - mu) * rstd * lw.y + lb.y;
        o4.z = (v.z - mu) * rstd * lw.z + lb.z;
        o4.w = (v.w - mu) * rstd * lw.w + lb.w;
        *(float4*)(LN_sh + r * 132 + 4 * lane) = o4;
    }
    __syncthreads();
    // phase B: Pe[128][128] = LN @ We  (same microkernel as gemm_body)
    int ty = tid >> 4, tx = tid & 15;
    u64t acc[8][4];
#pragma unroll
    for (int i = 0; i < 8; i++)
#pragma unroll
        for (int u = 0; u < 4; u++) acc[i][u] = 0ull;
    for (int kt = 0; kt < 4; ++kt) {
#pragma unroll
        for (int it = 0; it < 4; ++it) {
            int idx = tid + it * 256;
            int kk = idx >> 5, c4 = (idx & 31) << 2;
            *(float4*)(W_sh + kk * 132 + c4) =
                *(const float4*)(We + (size_t)(kt * 32 + kk) * 128 + c4);
        }
        __syncthreads();
#pragma unroll
        for (int kk = 0; kk < 32; ++kk) {
            int k = kt * 32 + kk;
            u64t w2[4];
            {
                const ulonglong2* wp = (const ulonglong2*)(W_sh + kk * 132 + 8 * tx);
                ulonglong2 w01 = wp[0];
                ulonglong2 w23 = wp[1];
                w2[0] = w01.x; w2[1] = w01.y; w2[2] = w23.x; w2[3] = w23.y;
            }
#pragma unroll
            for (int i = 0; i < 8; i++) {
                u64t a2 = pack2(LN_sh[(8 * ty + i) * 132 + k]);
                ffma2(acc[i][0], a2, w2[0]);
                ffma2(acc[i][1], a2, w2[1]);
                ffma2(acc[i][2], a2, w2[2]);
                ffma2(acc[i][3], a2, w2[3]);
            }
        }
        __syncthreads();
    }
    // stash Pe into LN_sh (LN values dead now)
#pragma unroll
    for (int i = 0; i < 8; i++) {
        float2 p0 = unpack2(acc[i][0]), p1 = unpack2(acc[i][1]);
        float2 p2 = unpack2(acc[i][2]), p3 = unpack2(acc[i][3]);
        *(float4*)(LN_sh + (8 * ty + i) * 132 + 8 * tx)     = make_float4(p0.x, p0.y, p1.x, p1.y);
        *(float4*)(LN_sh + (8 * ty + i) * 132 + 8 * tx + 4) = make_float4(p2.x, p2.y, p3.x, p3.y);
    }
    __syncthreads();
    // phase C: per-edge score, exp, scatter (16 edges per warp)
    const float inv = 0.17677669529663687f;  // 1/sqrt(32)
    int head = lane >> 3;
#pragma unroll
    for (int j = 0; j < 16; j++) {
        int r = w * 16 + j;
        int e = e0 + r;
        if (e >= E) break;
        int si = s_sh[r], di = d_sh[r];
        float4 kq = *(const float4*)(Kv + (size_t)si * 128 + 4 * lane);
        float4 qv = *(const float4*)(Q  + (size_t)di * 128 + 4 * lane);
        float4 pe = *(float4*)(LN_sh + r * 132 + 4 * lane);
        float t = clip5(kq.x * qv.x * inv) * pe.x + clip5(kq.y * qv.y * inv) * pe.y
                + clip5(kq.z * qv.z * inv) * pe.z + clip5(kq.w * qv.w * inv) * pe.w;
        t += __shfl_xor_sync(0xffffffffu, t, 1);
        t += __shfl_xor_sync(0xffffffffu, t, 2);
        t += __shfl_xor_sync(0xffffffffu, t, 4);
        float s = expf(clip5(t));
        float4 vv = *(const float4*)(V + (size_t)si * 128 + 4 * lane);
        float* dp = wV + (size_t)di * 128 + 4 * lane;
        red_add_v4(dp, vv.x * s, vv.y * s, vv.z * s, vv.w * s);
        if ((lane & 7) == 0) atomicAdd(z + (size_t)di * 4 + head, s);
    }
}

// ---------------- attn = wV / (z + 1e-6) ----------------
__global__ void attn_kernel(const float* __restrict__ wV, const float* __restrict__ z,
                            float* __restrict__ outp, int N) {
    int i = blockIdx.x * blockDim.x + threadIdx.x;  // over N*32 float4s
    if (i >= N * 32) return;
    int n = i >> 5;
    int head = (i & 31) >> 3;
    float invz = 1.f / (z[(size_t)n * 4 + head] + 1e-6f);
    float4 v = *(const float4*)(wV + (size_t)i * 4);
    v.x *= invz; v.y *= invz; v.z *= invz; v.w *= invz;
    *(float4*)(outp + (size_t)i * 4) = v;
}

// ---------------- Set2Set: one block per graph, all 3 iterations internal ----------------
__global__ void __launch_bounds__(256) set2set_kernel(
    const float* __restrict__ nf, const int* __restrict__ gid,
    const float* __restrict__ W_ih, const float* __restrict__ W_hh,
    const float* __restrict__ b_ih, const float* __restrict__ b_hh,
    float* __restrict__ ener, float* __restrict__ out, int N) {
    __shared__ float qs[256], hh[128], cc[128], gates[512], rsh[8 * 128], red[16];
    int tid = threadIdx.x, lane = tid & 31, w = tid >> 5;
    int g = blockIdx.x;
    int lo, hi;
    {
        int a = 0, b = N;
        while (a < b) { int m = (a + b) >> 1; if (gid[m] < g) a = m + 1; else b = m; }
        lo = a;
        b = N;
        while (a < b) { int m = (a + b) >> 1; if (gid[m] < g + 1) a = m + 1; else b = m; }
        hi = a;
    }
    qs[tid] = 0.f;
    if (tid < 128) { hh[tid] = 0.f; cc[tid] = 0.f; }
    __syncthreads();

    for (int it = 0; it < 3; ++it) {
        for (int j = tid; j < 512; j += 256) {
            float acc = b_ih[j] + b_hh[j];
            const float* wi = W_ih + (size_t)j * 256;
#pragma unroll 8
            for (int k2 = 0; k2 < 256; k2++) acc += qs[k2] * wi[k2];
            const float* whp = W_hh + (size_t)j * 128;
#pragma unroll 8
            for (int k2 = 0; k2 < 128; k2++) acc += hh[k2] * whp[k2];
            gates[j] = acc;
        }
        __syncthreads();
        if (tid < 128) {
            float c = sigm(gates[128 + tid]) * cc[tid] + sigm(gates[tid]) * tanhf(gates[256 + tid]);
            cc[tid] = c;
            hh[tid] = sigm(gates[384 + tid]) * tanhf(c);
        }
        __syncthreads();
        float mloc = -INFINITY;
        float4 h4 = *(float4*)&hh[4 * lane];
        for (int n = lo + w; n < hi; n += 8) {
            float4 a4 = *(const float4*)(nf + (size_t)n * 128 + 4 * lane);
            float t = a4.x * h4.x + a4.y * h4.y + a4.z * h4.z + a4.w * h4.w;
#pragma unroll
            for (int o = 16; o; o >>= 1) t += __shfl_xor_sync(0xffffffffu, t, o);
            if (lane == 0) ener[n] = t;
            mloc = fmaxf(mloc, t);
        }
#pragma unroll
        for (int o = 16; o; o >>= 1) mloc = fmaxf(mloc, __shfl_xor_sync(0xffffffffu, mloc, o));
        if (lane == 0) red[w] = mloc;
        __syncthreads();
        if (tid == 0) {
            float m = -INFINITY;
            for (int i = 0; i < 8; i++) m = fmaxf(m, red[i]);
            red[8] = m;
        }
        __syncthreads();
        float m = red[8];
        float dloc = 0.f;
        for (int n = lo + tid; n < hi; n += 256) dloc += expf(ener[n] - m);
#pragma unroll
        for (int o = 16; o; o >>= 1) dloc += __shfl_xor_sync(0xffffffffu, dloc, o);
        __syncthreads();
        if (lane == 0) red[w] = dloc;
        __syncthreads();
        if (tid == 0) {
            float d = 0.f;
            for (int i = 0; i < 8; i++) d += red[i];
            red[9] = d;
        }
        __syncthreads();
        float invd = 1.f / red[9];
        float4 racc = make_float4(0.f, 0.f, 0.f, 0.f);
        for (int n = lo + w; n < hi; n += 8) {
            float coef = expf(ener[n] - m) * invd;
            float4 a4 = *(const float4*)(nf + (size_t)n * 128 + 4 * lane);
            racc.x += coef * a4.x; racc.y += coef * a4.y;
            racc.z += coef * a4.z; racc.w += coef * a4.w;
        }
        *(float4*)&rsh[w * 128 + 4 * lane] = racc;
        __syncthreads();
        if (tid < 128) {
            float ro = 0.f;
#pragma unroll
            for (int i = 0; i < 8; i++) ro += rsh[i * 128 + tid];
            qs[tid] = hh[tid];
            qs[128 + tid] = ro;
        }
        __syncthreads();
    }
    out[(size_t)g * 256 + tid] = qs[tid];
}

// ---------------- launch ----------------
extern "C" void kernel_launch(void* const* d_in, const int* in_sizes, int n_in,
                              void* d_out, int out_size) {
    const float* node = (const float*)d_in[0];
    const float* edge = (const float*)d_in[1];
    const float* Wq = (const float*)d_in[2];
    const float* Wk = (const float*)d_in[3];
    const float* Wv = (const float*)d_in[4];
    const float* We = (const float*)d_in[5];
    const float* Wo = (const float*)d_in[6];
    const float* bo = (const float*)d_in[7];
    const float* W1 = (const float*)d_in[8];
    const float* W2 = (const float*)d_in[9];
    const float* l1nw = (const float*)d_in[10];
    const float* l1nb = (const float*)d_in[11];
    const float* l1ew = (const float*)d_in[12];
    const float* l1eb = (const float*)d_in[13];
    const float* l2w = (const float*)d_in[14];
    const float* l2b = (const float*)d_in[15];
    const float* Wih = (const float*)d_in[16];
    const float* Whh = (const float*)d_in[17];
    const float* bih = (const float*)d_in[18];
    const float* bhh = (const float*)d_in[19];
    const int* src = (const int*)d_in[20];
    const int* dst = (const int*)d_in[21];
    const int* gid = (const int*)d_in[22];

    int N = in_sizes[0] / 128;
    int E = in_sizes[20];
    int G = out_size / 256;

    float *b1, *q, *k, *v, *x, *wv, *z, *t, *en;
    cudaGetSymbolAddress((void**)&b1, g_b1);
    cudaGetSymbolAddress((void**)&q,  g_Q);
    cudaGetSymbolAddress((void**)&k,  g_K);
    cudaGetSymbolAddress((void**)&v,  g_V);
    cudaGetSymbolAddress((void**)&x,  g_x);
    cudaGetSymbolAddress((void**)&wv, g_wV);
    cudaGetSymbolAddress((void**)&z,  g_z);
    cudaGetSymbolAddress((void**)&t,  g_t);
    cudaGetSymbolAddress((void**)&en, g_en);

    const int edge_smem = (128 * 132 + 32 * 132) * 4 + 2 * 128 * 4;
    cudaFuncSetAttribute(edge_kernel, cudaFuncAttributeMaxDynamicSharedMemorySize, edge_smem);

    int gnodes = (N + 127) / 128;

    // 1) LN(node) -> b1
    ln_kernel<<<(N + 7) / 8, 256>>>(node, b1, l1nw, l1nb, N);
    // 2) Q, K, V (single fused launch)
    qkv_kernel<<<dim3(gnodes, 3), 256>>>(b1, Wq, Wk, Wv, q, k, v, N);
    // 3) zero accumulators
    fzero_kernel<<<(N * 32 + 255) / 256, 256>>>((float4*)wv, N * 32);
    fzero_kernel<<<(N + 255) / 256, 256>>>((float4*)z, N);
    // 4) fused edge kernel (128-edge tiles)
    edge_kernel<<<(E + 127) / 128, 256, edge_smem>>>(edge, l1ew, l1eb, We, src, dst,
                                                     q, k, v, wv, z, E);
    // 5) attn -> b1
    attn_kernel<<<(N * 32 + 255) / 256, 256>>>(wv, z, b1, N);
    // 6) x = node + attn@Wo + bo
    gemm_kernel<1><<<dim3(gnodes, 1), 256>>>(b1, Wo, bo, node, x, N, 128, 128);
    // 7) y = LN2(x) -> q (reuse)
    ln_kernel<<<(N + 7) / 8, 256>>>(x, q, l2w, l2b, N);
    // 8) t = silu(y @ W1)   [N,256]
    gemm_kernel<2><<<dim3(gnodes, 2), 256>>>(q, W1, nullptr, nullptr, t, N, 128, 256);
    // 9) nf = x + t @ W2 -> k (reuse)
    gemm_kernel<3><<<dim3(gnodes, 1), 256>>>(t, W2, nullptr, x, k, N, 256, 128);
    // 10) Set2Set readout (3 iterations inside)
    set2set_kernel<<<G, 256>>>(k, gid, Wih, Whh, bih, bhh, en, (float*)d_out, N);
}

// round 5
// speedup vs baseline: 1.4045x; 1.0343x over previous
#include <cuda_runtime.h>
#include <math.h>

#define MAXN 50048
#define MAXE 600064

// ---------------- scratch (static device globals; no allocation) ----------------
__device__ float g_b1[(size_t)MAXN * 128];   // hn -> attn (reused)
__device__ float g_Q [(size_t)MAXN * 128];   // Q -> y (reused)
__device__ float g_K [(size_t)MAXN * 128];   // K -> nf (reused)
__device__ float g_V [(size_t)MAXN * 128];
__device__ float g_x [(size_t)MAXN * 128];
__device__ float g_wV[(size_t)MAXN * 128];
__device__ float g_z [(size_t)MAXN * 4];
__device__ float g_t [(size_t)MAXN * 256];
__device__ float g_en[(size_t)MAXN];

__device__ __forceinline__ float clip5(float x) { return fminf(fmaxf(x, -5.f), 5.f); }
__device__ __forceinline__ float sigm(float x)  { return 1.f / (1.f + expf(-x)); }

// ---- packed f32x2 helpers (FFMA2: 2 MACs per issue slot; fp32-exact) ----
typedef unsigned long long u64t;
__device__ __forceinline__ u64t pack2(float x) {
    u64t r; asm("mov.b64 %0, {%1, %1};" : "=l"(r) : "f"(x)); return r;
}
__device__ __forceinline__ void ffma2(u64t& d, u64t a, u64t b) {
    asm("fma.rn.f32x2 %0, %1, %2, %0;" : "+l"(d) : "l"(a), "l"(b));
}
__device__ __forceinline__ float2 unpack2(u64t v) {
    float2 r; asm("mov.b64 {%0, %1}, %2;" : "=f"(r.x), "=f"(r.y) : "l"(v)); return r;
}
__device__ __forceinline__ void red_add_v4(float* p, float a, float b, float c, float d) {
    asm volatile("red.global.add.v4.f32 [%0], {%1,%2,%3,%4};"
                 :: "l"(p), "f"(a), "f"(b), "f"(c), "f"(d) : "memory");
}
__device__ __forceinline__ void red_add_f(float* p, float v) {
    asm volatile("red.global.add.f32 [%0], %1;" :: "l"(p), "f"(v) : "memory");
}

// ---------------- zero fill ----------------
__global__ void fzero_kernel(float4* __restrict__ p, int n4) {
    int i = blockIdx.x * blockDim.x + threadIdx.x;
    if (i < n4) p[i] = make_float4(0.f, 0.f, 0.f, 0.f);
}

// ---------------- row LayerNorm (warp per 128-wide row) ----------------
__global__ void ln_kernel(const float* __restrict__ in, float* __restrict__ out,
                          const float* __restrict__ w, const float* __restrict__ b, int rows) {
    int warp = (blockIdx.x * blockDim.x + threadIdx.x) >> 5;
    int lane = threadIdx.x & 31;
    if (warp >= rows) return;
    float4 v = *(const float4*)(in + (size_t)warp * 128 + 4 * lane);
    float s  = v.x + v.y + v.z + v.w;
    float sq = v.x * v.x + v.y * v.y + v.z * v.z + v.w * v.w;
#pragma unroll
    for (int o = 16; o; o >>= 1) {
        s  += __shfl_xor_sync(0xffffffffu, s,  o);
        sq += __shfl_xor_sync(0xffffffffu, sq, o);
    }
    float mu   = s * (1.f / 128.f);
    float rstd = rsqrtf(sq * (1.f / 128.f) - mu * mu + 1e-5f);
    float4 wv = *(const float4*)(w + 4 * lane);
    float4 bv = *(const float4*)(b + 4 * lane);
    float4 o4;
    o4.x = (v.x - mu) * rstd * wv.x + bv.x;
    o4.y = (v.y - mu) * rstd * wv.y + bv.y;
    o4.z = (v.z - mu) * rstd * wv.z + bv.z;
    o4.w = (v.w - mu) * rstd * wv.w + bv.w;
    *(float4*)(out + (size_t)warp * 128 + 4 * lane) = o4;
}

// ---------------- GEMM body: tile 128x128, BK=32, 8x8/thread, FFMA2, prefetch ----------
// Column ownership: thread tx owns cols {4tx..4tx+3} and {64+4tx..64+4tx+3} (conflict-free).
// A stored duplicated (f32x2 pairs) in smem: u64 A2[128][34].
// EPI: 0 none, 1 += bias[c] + res[r,c], 2 SiLU, 3 += res[r,c]
#define A2_STRIDE 34
template <int EPI>
__device__ __forceinline__ void gemm_body(
    const float* __restrict__ A, const float* __restrict__ W,
    const float* __restrict__ bias, const float* __restrict__ res,
    float* __restrict__ C, int M, int K, int NC, int row0, int cb,
    u64t* A2_sh /*[128][34]*/, float* W_sh /*[32][128]*/) {
    int tid = threadIdx.x;
    int ty = tid >> 4, tx = tid & 15;
    u64t acc[8][4];
#pragma unroll
    for (int i = 0; i < 8; i++)
#pragma unroll
        for (int u = 0; u < 4; u++) acc[i][u] = 0ull;

    int nkt = K >> 5;
    float4 pa[4], pw[4];
    // prefetch kt = 0
#pragma unroll
    for (int it = 0; it < 4; ++it) {
        int idx = tid + it * 256;
        int r = idx >> 3, c4 = (idx & 7) << 2;
        pa[it] = make_float4(0.f, 0.f, 0.f, 0.f);
        if (row0 + r < M) pa[it] = *(const float4*)(A + (size_t)(row0 + r) * K + c4);
        int kk = idx >> 5, wc = (idx & 31) << 2;
        pw[it] = *(const float4*)(W + (size_t)kk * NC + cb + wc);
    }
    for (int kt = 0; kt < nkt; ++kt) {
        // stage registers -> smem
#pragma unroll
        for (int it = 0; it < 4; ++it) {
            int idx = tid + it * 256;
            int r = idx >> 3, c4 = (idx & 7) << 2;
            ulonglong2* p = (ulonglong2*)(A2_sh + (size_t)r * A2_STRIDE + c4);
            ulonglong2 d0; d0.x = pack2(pa[it].x); d0.y = pack2(pa[it].y);
            ulonglong2 d1; d1.x = pack2(pa[it].z); d1.y = pack2(pa[it].w);
            p[0] = d0; p[1] = d1;
            int kk = idx >> 5, wc = (idx & 31) << 2;
            *(float4*)(W_sh + kk * 128 + wc) = pw[it];
        }
        __syncthreads();
        // prefetch kt+1
        if (kt + 1 < nkt) {
#pragma unroll
            for (int it = 0; it < 4; ++it) {
                int idx = tid + it * 256;
                int r = idx >> 3, c4 = (idx & 7) << 2;
                pa[it] = make_float4(0.f, 0.f, 0.f, 0.f);
                if (row0 + r < M)
                    pa[it] = *(const float4*)(A + (size_t)(row0 + r) * K + (kt + 1) * 32 + c4);
                int kk = idx >> 5, wc = (idx & 31) << 2;
                pw[it] = *(const float4*)(W + (size_t)((kt + 1) * 32 + kk) * NC + cb + wc);
            }
        }
        // compute: 2 k-steps per iteration
#pragma unroll
        for (int kkp = 0; kkp < 16; ++kkp) {
            const float* wr0 = W_sh + (2 * kkp) * 128;
            ulonglong2 t0 = *(const ulonglong2*)(wr0 + 4 * tx);
            ulonglong2 t1 = *(const ulonglong2*)(wr0 + 64 + 4 * tx);
            ulonglong2 t2 = *(const ulonglong2*)(wr0 + 128 + 4 * tx);
            ulonglong2 t3 = *(const ulonglong2*)(wr0 + 192 + 4 * tx);
#pragma unroll
            for (int i = 0; i < 8; i++) {
                ulonglong2 a01 = *(const ulonglong2*)(A2_sh + (size_t)(8 * ty + i) * A2_STRIDE + 2 * kkp);
                ffma2(acc[i][0], a01.x, t0.x);
                ffma2(acc[i][1], a01.x, t0.y);
                ffma2(acc[i][2], a01.x, t1.x);
                ffma2(acc[i][3], a01.x, t1.y);
                ffma2(acc[i][0], a01.y, t2.x);
                ffma2(acc[i][1], a01.y, t2.y);
                ffma2(acc[i][2], a01.y, t3.x);
                ffma2(acc[i][3], a01.y, t3.y);
            }
        }
        __syncthreads();
    }
    // epilogue: cols c0 = cb + 4tx, c1 = cb + 64 + 4tx
    int c0 = cb + 4 * tx, c1 = cb + 64 + 4 * tx;
#pragma unroll
    for (int i = 0; i < 8; i++) {
        int r = row0 + 8 * ty + i;
        if (r >= M) continue;
        float2 p0 = unpack2(acc[i][0]), p1 = unpack2(acc[i][1]);
        float2 p2 = unpack2(acc[i][2]), p3 = unpack2(acc[i][3]);
        float o[8] = {p0.x, p0.y, p1.x, p1.y, p2.x, p2.y, p3.x, p3.y};
        if (EPI == 1) {
            float4 b0 = *(const float4*)(bias + c0);
            float4 b1 = *(const float4*)(bias + c1);
            float4 r0 = *(const float4*)(res + (size_t)r * NC + c0);
            float4 r1 = *(const float4*)(res + (size_t)r * NC + c1);
            o[0] += b0.x + r0.x; o[1] += b0.y + r0.y; o[2] += b0.z + r0.z; o[3] += b0.w + r0.w;
            o[4] += b1.x + r1.x; o[5] += b1.y + r1.y; o[6] += b1.z + r1.z; o[7] += b1.w + r1.w;
        }
        if (EPI == 2) {
#pragma unroll
            for (int u = 0; u < 8; u++) o[u] = o[u] / (1.f + expf(-o[u]));
        }
        if (EPI == 3) {
            float4 r0 = *(const float4*)(res + (size_t)r * NC + c0);
            float4 r1 = *(const float4*)(res + (size_t)r * NC + c1);
            o[0] += r0.x; o[1] += r0.y; o[2] += r0.z; o[3] += r0.w;
            o[4] += r1.x; o[5] += r1.y; o[6] += r1.z; o[7] += r1.w;
        }
        *(float4*)(C + (size_t)r * NC + c0) = make_float4(o[0], o[1], o[2], o[3]);
        *(float4*)(C + (size_t)r * NC + c1) = make_float4(o[4], o[5], o[6], o[7]);
    }
}

#define GEMM_SMEM (128 * A2_STRIDE * 8 + 32 * 128 * 4)

template <int EPI>
__global__ void __launch_bounds__(256, 2) gemm_kernel(
    const float* __restrict__ A, const float* __restrict__ W,
    const float* __restrict__ bias, const float* __restrict__ res,
    float* __restrict__ C, int M, int K, int NC) {
    extern __shared__ char dsh[];
    u64t* A2_sh = (u64t*)dsh;
    float* W_sh = (float*)(dsh + 128 * A2_STRIDE * 8);
    gemm_body<EPI>(A, W, bias, res, C, M, K, NC, blockIdx.x * 128, blockIdx.y * 128, A2_sh, W_sh);
}

// fused Q/K/V: grid.y selects the weight + output
__global__ void __launch_bounds__(256, 2) qkv_kernel(
    const float* __restrict__ A,
    const float* __restrict__ Wq, const float* __restrict__ Wk, const float* __restrict__ Wv,
    float* __restrict__ Q, float* __restrict__ Ko, float* __restrict__ V, int M) {
    extern __shared__ char dsh[];
    u64t* A2_sh = (u64t*)dsh;
    float* W_sh = (float*)(dsh + 128 * A2_STRIDE * 8);
    const float* W = (blockIdx.y == 0) ? Wq : (blockIdx.y == 1) ? Wk : Wv;
    float* C       = (blockIdx.y == 0) ? Q  : (blockIdx.y == 1) ? Ko : V;
    gemm_body<0>(A, W, nullptr, nullptr, C, M, 128, 128, blockIdx.x * 128, 0, A2_sh, W_sh);
}

// ---------------- fused edge kernel: LN(edge) -> Pe GEMM -> score/exp -> scatter --------
// tile = 128 edges; LN_sh stride 132 floats (528B = 33*16 — float4-aligned every row)
#define LN_STRIDE 132
__global__ void __launch_bounds__(256, 2) edge_kernel(
    const float* __restrict__ ef, const float* __restrict__ lnw, const float* __restrict__ lnb,
    const float* __restrict__ We, const int* __restrict__ src, const int* __restrict__ dst,
    const float* __restrict__ Q, const float* __restrict__ Kv, const float* __restrict__ V,
    float* __restrict__ wV, float* __restrict__ z, int E) {
    extern __shared__ float sh[];
    float* LN_sh = sh;                          // [128][132] ln rows, later Pe
    float* W_sh  = sh + 128 * LN_STRIDE;        // [32][128]
    int* s_sh = (int*)(W_sh + 32 * 128);        // [128]
    int* d_sh = s_sh + 128;                     // [128]

    int tid = threadIdx.x, lane = tid & 31, w = tid >> 5;
    int e0 = blockIdx.x * 128;
    if (tid < 128) {
        int e = e0 + tid;
        s_sh[tid] = (e < E) ? src[e] : 0;
        d_sh[tid] = (e < E) ? dst[e] : 0;
    }
    // prefetch first W tile
    float4 pw[4];
#pragma unroll
    for (int it = 0; it < 4; ++it) {
        int idx = tid + it * 256;
        int kk = idx >> 5, wc = (idx & 31) << 2;
        pw[it] = *(const float4*)(We + (size_t)kk * 128 + wc);
    }
    float4 lw = *(const float4*)(lnw + 4 * lane);
    float4 lb = *(const float4*)(lnb + 4 * lane);
    // phase A: LN of 16 edge rows per warp
#pragma unroll
    for (int i = 0; i < 16; i++) {
        int r = w * 16 + i;
        int e = e0 + r;
        float4 v = make_float4(0.f, 0.f, 0.f, 0.f);
        if (e < E) v = *(const float4*)(ef + (size_t)e * 128 + 4 * lane);
        float s  = v.x + v.y + v.z + v.w;
        float sq = v.x * v.x + v.y * v.y + v.z * v.z + v.w * v.w;
#pragma unroll
        for (int o = 16; o; o >>= 1) {
            s  += __shfl_xor_sync(0xffffffffu, s,  o);
            sq += __shfl_xor_sync(0xffffffffu, sq, o);
        }
        float mu   = s * (1.f / 128.f);
        float rstd = rsqrtf(sq * (1.f / 128.f) - mu * mu + 1e-5f);
        float4 o4;
        o4.x = (v.x - mu) * rstd * lw.x + lb.x;
        o4.y = (v.y - mu) * rstd * lw.y + lb.y;
        o4.z = (v.z - mu) * rstd * lw.z + lb.z;
        o4.w = (v.w - mu) * rstd * lw.w + lb.w;
        *(float4*)(LN_sh + r * LN_STRIDE + 4 * lane) = o4;
    }
    __syncthreads();
    // phase B: Pe[128][128] = LN @ We
    int ty = tid >> 4, tx = tid & 15;
    u64t acc[8][4];
#pragma unroll
    for (int i = 0; i < 8; i++)
#pragma unroll
        for (int u = 0; u < 4; u++) acc[i][u] = 0ull;
    for (int kt = 0; kt < 4; ++kt) {
#pragma unroll
        for (int it = 0; it < 4; ++it) {
            int idx = tid + it * 256;
            int kk = idx >> 5, wc = (idx & 31) << 2;
            *(float4*)(W_sh + kk * 128 + wc) = pw[it];
        }
        __syncthreads();
        if (kt < 3) {
#pragma unroll
            for (int it = 0; it < 4; ++it) {
                int idx = tid + it * 256;
                int kk = idx >> 5, wc = (idx & 31) << 2;
                pw[it] = *(const float4*)(We + (size_t)((kt + 1) * 32 + kk) * 128 + wc);
            }
        }
#pragma unroll
        for (int kkp = 0; kkp < 16; ++kkp) {
            const float* wr0 = W_sh + (2 * kkp) * 128;
            ulonglong2 t0 = *(const ulonglong2*)(wr0 + 4 * tx);
            ulonglong2 t1 = *(const ulonglong2*)(wr0 + 64 + 4 * tx);
            ulonglong2 t2 = *(const ulonglong2*)(wr0 + 128 + 4 * tx);
            ulonglong2 t3 = *(const ulonglong2*)(wr0 + 192 + 4 * tx);
#pragma unroll
            for (int i = 0; i < 8; i++) {
                float2 a01 = *(const float2*)(LN_sh + (size_t)(8 * ty + i) * LN_STRIDE + kt * 32 + 2 * kkp);
                u64t a0 = pack2(a01.x), a1 = pack2(a01.y);
                ffma2(acc[i][0], a0, t0.x);
                ffma2(acc[i][1], a0, t0.y);
                ffma2(acc[i][2], a0, t1.x);
                ffma2(acc[i][3], a0, t1.y);
                ffma2(acc[i][0], a1, t2.x);
                ffma2(acc[i][1], a1, t2.y);
                ffma2(acc[i][2], a1, t3.x);
                ffma2(acc[i][3], a1, t3.y);
            }
        }
        __syncthreads();
    }
    // stash Pe into LN_sh (LN values dead now)
#pragma unroll
    for (int i = 0; i < 8; i++) {
        float2 p0 = unpack2(acc[i][0]), p1 = unpack2(acc[i][1]);
        float2 p2 = unpack2(acc[i][2]), p3 = unpack2(acc[i][3]);
        *(float4*)(LN_sh + (8 * ty + i) * LN_STRIDE + 4 * tx)      = make_float4(p0.x, p0.y, p1.x, p1.y);
        *(float4*)(LN_sh + (8 * ty + i) * LN_STRIDE + 64 + 4 * tx) = make_float4(p2.x, p2.y, p3.x, p3.y);
    }
    __syncthreads();
    // phase C: per-edge score, exp, scatter (16 edges per warp, prefetched)
    const float inv = 0.17677669529663687f;  // 1/sqrt(32)
    int head = lane >> 3;
    int base = w * 16;
    int si = s_sh[base], di = d_sh[base];
    float4 kq = *(const float4*)(Kv + (size_t)si * 128 + 4 * lane);
    float4 qv = *(const float4*)(Q  + (size_t)di * 128 + 4 * lane);
    float4 vv = *(const float4*)(V  + (size_t)si * 128 + 4 * lane);
#pragma unroll
    for (int j = 0; j < 16; j++) {
        int e = e0 + base + j;
        float4 kqc = kq, qvc = qv, vvc = vv;
        int dic = di;
        if (j < 15) {
            int sn = s_sh[base + j + 1], dn = d_sh[base + j + 1];
            kq = *(const float4*)(Kv + (size_t)sn * 128 + 4 * lane);
            qv = *(const float4*)(Q  + (size_t)dn * 128 + 4 * lane);
            vv = *(const float4*)(V  + (size_t)sn * 128 + 4 * lane);
            di = dn;
        }
        if (e < E) {
            float4 pe = *(float4*)(LN_sh + (base + j) * LN_STRIDE + 4 * lane);
            float t = clip5(kqc.x * qvc.x * inv) * pe.x + clip5(kqc.y * qvc.y * inv) * pe.y
                    + clip5(kqc.z * qvc.z * inv) * pe.z + clip5(kqc.w * qvc.w * inv) * pe.w;
            t += __shfl_xor_sync(0xffffffffu, t, 1);
            t += __shfl_xor_sync(0xffffffffu, t, 2);
            t += __shfl_xor_sync(0xffffffffu, t, 4);
            float s = expf(clip5(t));
            float* dp = wV + (size_t)dic * 128 + 4 * lane;
            red_add_v4(dp, vvc.x * s, vvc.y * s, vvc.z * s, vvc.w * s);
            if ((lane & 7) == 0) red_add_f(z + (size_t)dic * 4 + head, s);
        }
    }
}
#define EDGE_SMEM (128 * LN_STRIDE * 4 + 32 * 128 * 4 + 2 * 128 * 4)

// ---------------- attn = wV / (z + 1e-6) ----------------
__global__ void attn_kernel(const float* __restrict__ wV, const float* __restrict__ z,
                            float* __restrict__ outp, int N) {
    int i = blockIdx.x * blockDim.x + threadIdx.x;  // over N*32 float4s
    if (i >= N * 32) return;
    int n = i >> 5;
    int head = (i & 31) >> 3;
    float invz = 1.f / (z[(size_t)n * 4 + head] + 1e-6f);
    float4 v = *(const float4*)(wV + (size_t)i * 4);
    v.x *= invz; v.y *= invz; v.z *= invz; v.w *= invz;
    *(float4*)(outp + (size_t)i * 4) = v;
}

// ---------------- Set2Set: one block per graph, all 3 iterations internal ----------------
__global__ void __launch_bounds__(256) set2set_kernel(
    const float* __restrict__ nf, const int* __restrict__ gid,
    const float* __restrict__ W_ih, const float* __restrict__ W_hh,
    const float* __restrict__ b_ih, const float* __restrict__ b_hh,
    float* __restrict__ ener, float* __restrict__ out, int N) {
    __shared__ float qs[256], hh[128], cc[128], gates[512], rsh[8 * 128], red[16];
    int tid = threadIdx.x, lane = tid & 31, w = tid >> 5;
    int g = blockIdx.x;
    int lo, hi;
    {
        int a = 0, b = N;
        while (a < b) { int m = (a + b) >> 1; if (gid[m] < g) a = m + 1; else b = m; }
        lo = a;
        b = N;
        while (a < b) { int m = (a + b) >> 1; if (gid[m] < g + 1) a = m + 1; else b = m; }
        hi = a;
    }
    qs[tid] = 0.f;
    if (tid < 128) { hh[tid] = 0.f; cc[tid] = 0.f; }
    __syncthreads();

    for (int it = 0; it < 3; ++it) {
        for (int j = tid; j < 512; j += 256) {
            float acc = b_ih[j] + b_hh[j];
            const float* wi = W_ih + (size_t)j * 256;
#pragma unroll 8
            for (int k2 = 0; k2 < 256; k2++) acc += qs[k2] * wi[k2];
            const float* whp = W_hh + (size_t)j * 128;
#pragma unroll 8
            for (int k2 = 0; k2 < 128; k2++) acc += hh[k2] * whp[k2];
            gates[j] = acc;
        }
        __syncthreads();
        if (tid < 128) {
            float c = sigm(gates[128 + tid]) * cc[tid] + sigm(gates[tid]) * tanhf(gates[256 + tid]);
            cc[tid] = c;
            hh[tid] = sigm(gates[384 + tid]) * tanhf(c);
        }
        __syncthreads();
        float mloc = -INFINITY;
        float4 h4 = *(float4*)&hh[4 * lane];
        for (int n = lo + w; n < hi; n += 8) {
            float4 a4 = *(const float4*)(nf + (size_t)n * 128 + 4 * lane);
            float t = a4.x * h4.x + a4.y * h4.y + a4.z * h4.z + a4.w * h4.w;
#pragma unroll
            for (int o = 16; o; o >>= 1) t += __shfl_xor_sync(0xffffffffu, t, o);
            if (lane == 0) ener[n] = t;
            mloc = fmaxf(mloc, t);
        }
#pragma unroll
        for (int o = 16; o; o >>= 1) mloc = fmaxf(mloc, __shfl_xor_sync(0xffffffffu, mloc, o));
        if (lane == 0) red[w] = mloc;
        __syncthreads();
        if (tid == 0) {
            float m = -INFINITY;
            for (int i = 0; i < 8; i++) m = fmaxf(m, red[i]);
            red[8] = m;
        }
        __syncthreads();
        float m = red[8];
        float dloc = 0.f;
        for (int n = lo + tid; n < hi; n += 256) dloc += expf(ener[n] - m);
#pragma unroll
        for (int o = 16; o; o >>= 1) dloc += __shfl_xor_sync(0xffffffffu, dloc, o);
        __syncthreads();
        if (lane == 0) red[w] = dloc;
        __syncthreads();
        if (tid == 0) {
            float d = 0.f;
            for (int i = 0; i < 8; i++) d += red[i];
            red[9] = d;
        }
        __syncthreads();
        float invd = 1.f / red[9];
        float4 racc = make_float4(0.f, 0.f, 0.f, 0.f);
        for (int n = lo + w; n < hi; n += 8) {
            float coef = expf(ener[n] - m) * invd;
            float4 a4 = *(const float4*)(nf + (size_t)n * 128 + 4 * lane);
            racc.x += coef * a4.x; racc.y += coef * a4.y;
            racc.z += coef * a4.z; racc.w += coef * a4.w;
        }
        *(float4*)&rsh[w * 128 + 4 * lane] = racc;
        __syncthreads();
        if (tid < 128) {
            float ro = 0.f;
#pragma unroll
            for (int i = 0; i < 8; i++) ro += rsh[i * 128 + tid];
            qs[tid] = hh[tid];
            qs[128 + tid] = ro;
        }
        __syncthreads();
    }
    out[(size_t)g * 256 + tid] = qs[tid];
}

// ---------------- launch ----------------
extern "C" void kernel_launch(void* const* d_in, const int* in_sizes, int n_in,
                              void* d_out, int out_size) {
    const float* node = (const float*)d_in[0];
    const float* edge = (const float*)d_in[1];
    const float* Wq = (const float*)d_in[2];
    const float* Wk = (const float*)d_in[3];
    const float* Wv = (const float*)d_in[4];
    const float* We = (const float*)d_in[5];
    const float* Wo = (const float*)d_in[6];
    const float* bo = (const float*)d_in[7];
    const float* W1 = (const float*)d_in[8];
    const float* W2 = (const float*)d_in[9];
    const float* l1nw = (const float*)d_in[10];
    const float* l1nb = (const float*)d_in[11];
    const float* l1ew = (const float*)d_in[12];
    const float* l1eb = (const float*)d_in[13];
    const float* l2w = (const float*)d_in[14];
    const float* l2b = (const float*)d_in[15];
    const float* Wih = (const float*)d_in[16];
    const float* Whh = (const float*)d_in[17];
    const float* bih = (const float*)d_in[18];
    const float* bhh = (const float*)d_in[19];
    const int* src = (const int*)d_in[20];
    const int* dst = (const int*)d_in[21];
    const int* gid = (const int*)d_in[22];

    int N = in_sizes[0] / 128;
    int E = in_sizes[20];
    int G = out_size / 256;

    float *b1, *q, *k, *v, *x, *wv, *z, *t, *en;
    cudaGetSymbolAddress((void**)&b1, g_b1);
    cudaGetSymbolAddress((void**)&q,  g_Q);
    cudaGetSymbolAddress((void**)&k,  g_K);
    cudaGetSymbolAddress((void**)&v,  g_V);
    cudaGetSymbolAddress((void**)&x,  g_x);
    cudaGetSymbolAddress((void**)&wv, g_wV);
    cudaGetSymbolAddress((void**)&z,  g_z);
    cudaGetSymbolAddress((void**)&t,  g_t);
    cudaGetSymbolAddress((void**)&en, g_en);

    cudaFuncSetAttribute(edge_kernel, cudaFuncAttributeMaxDynamicSharedMemorySize, EDGE_SMEM);
    cudaFuncSetAttribute(qkv_kernel, cudaFuncAttributeMaxDynamicSharedMemorySize, GEMM_SMEM);
    cudaFuncSetAttribute(gemm_kernel<1>, cudaFuncAttributeMaxDynamicSharedMemorySize, GEMM_SMEM);
    cudaFuncSetAttribute(gemm_kernel<2>, cudaFuncAttributeMaxDynamicSharedMemorySize, GEMM_SMEM);
    cudaFuncSetAttribute(gemm_kernel<3>, cudaFuncAttributeMaxDynamicSharedMemorySize, GEMM_SMEM);

    int gnodes = (N + 127) / 128;

    // 1) LN(node) -> b1
    ln_kernel<<<(N + 7) / 8, 256>>>(node, b1, l1nw, l1nb, N);
    // 2) Q, K, V (single fused launch)
    qkv_kernel<<<dim3(gnodes, 3), 256, GEMM_SMEM>>>(b1, Wq, Wk, Wv, q, k, v, N);
    // 3) zero accumulators
    fzero_kernel<<<(N * 32 + 255) / 256, 256>>>((float4*)wv, N * 32);
    fzero_kernel<<<(N + 255) / 256, 256>>>((float4*)z, N);
    // 4) fused edge kernel (128-edge tiles)
    edge_kernel<<<(E + 127) / 128, 256, EDGE_SMEM>>>(edge, l1ew, l1eb, We, src, dst,
                                                     q, k, v, wv, z, E);
    // 5) attn -> b1
    attn_kernel<<<(N * 32 + 255) / 256, 256>>>(wv, z, b1, N);
    // 6) x = node + attn@Wo + bo
    gemm_kernel<1><<<dim3(gnodes, 1), 256, GEMM_SMEM>>>(b1, Wo, bo, node, x, N, 128, 128);
    // 7) y = LN2(x) -> q (reuse)
    ln_kernel<<<(N + 7) / 8, 256>>>(x, q, l2w, l2b, N);
    // 8) t = silu(y @ W1)   [N,256]
    gemm_kernel<2><<<dim3(gnodes, 2), 256, GEMM_SMEM>>>(q, W1, nullptr, nullptr, t, N, 128, 256);
    // 9) nf = x + t @ W2 -> k (reuse)
    gemm_kernel<3><<<dim3(gnodes, 1), 256, GEMM_SMEM>>>(t, W2, nullptr, x, k, N, 256, 128);
    // 10) Set2Set readout (3 iterations inside)
    set2set_kernel<<<G, 256>>>(k, gid, Wih, Whh, bih, bhh, en, (float*)d_out, N);
}

// round 6
// speedup vs baseline: 1.5364x; 1.0939x over previous
#include <cuda_runtime.h>
#include <math.h>
#include <stdint.h>

#define MAXN 50048
#define MAXE 600064

// ---------------- scratch (static device globals; no allocation) ----------------
__device__ float g_b1[(size_t)MAXN * 128];   // hn -> attn (reused)
__device__ float g_Q [(size_t)MAXN * 128];   // Q -> y (reused)
__device__ float g_K [(size_t)MAXN * 128];   // K -> nf (reused)
__device__ float g_V [(size_t)MAXN * 128];
__device__ float g_x [(size_t)MAXN * 128];
__device__ float g_wV[(size_t)MAXN * 128];
__device__ float g_z [(size_t)MAXN * 4];
__device__ float g_t [(size_t)MAXN * 256];
__device__ float g_en[(size_t)MAXN];

__device__ __forceinline__ float clip5(float x) { return fminf(fmaxf(x, -5.f), 5.f); }
__device__ __forceinline__ float sigm(float x)  { return 1.f / (1.f + expf(-x)); }

__device__ __forceinline__ void red_add_v4(float* p, float a, float b, float c, float d) {
    asm volatile("red.global.add.v4.f32 [%0], {%1,%2,%3,%4};"
                 :: "l"(p), "f"(a), "f"(b), "f"(c), "f"(d) : "memory");
}
__device__ __forceinline__ void red_add_f(float* p, float v) {
    asm volatile("red.global.add.f32 [%0], %1;" :: "l"(p), "f"(v) : "memory");
}

// ---- 3xTF32 helpers ----
// split x into hi (tf32-rounded, valid fp32) and lo (tf32 of remainder)
__device__ __forceinline__ void tf32split(float x, uint32_t& hi, uint32_t& lo) {
    uint32_t h; asm("cvt.rna.tf32.f32 %0, %1;" : "=r"(h) : "f"(x));
    float hf = __uint_as_float(h);
    float l = x - hf;
    uint32_t lr; asm("cvt.rna.tf32.f32 %0, %1;" : "=r"(lr) : "f"(l));
    hi = h; lo = lr;
}
// D += A(16x8 tf32) * B(8x8 tf32); standard m16n8k8 fragment layouts
__device__ __forceinline__ void mma8(float* d, const uint32_t* a, uint32_t b0, uint32_t b1) {
    asm volatile("mma.sync.aligned.m16n8k8.row.col.f32.tf32.tf32.f32 "
        "{%0,%1,%2,%3}, {%4,%5,%6,%7}, {%8,%9}, {%0,%1,%2,%3};"
        : "+f"(d[0]), "+f"(d[1]), "+f"(d[2]), "+f"(d[3])
        : "r"(a[0]), "r"(a[1]), "r"(a[2]), "r"(a[3]), "r"(b0), "r"(b1));
}

// ---------------- zero fill ----------------
__global__ void fzero_kernel(float4* __restrict__ p, int n4) {
    int i = blockIdx.x * blockDim.x + threadIdx.x;
    if (i < n4) p[i] = make_float4(0.f, 0.f, 0.f, 0.f);
}

// ---------------- row LayerNorm (warp per 128-wide row) ----------------
__global__ void ln_kernel(const float* __restrict__ in, float* __restrict__ out,
                          const float* __restrict__ w, const float* __restrict__ b, int rows) {
    int warp = (blockIdx.x * blockDim.x + threadIdx.x) >> 5;
    int lane = threadIdx.x & 31;
    if (warp >= rows) return;
    float4 v = *(const float4*)(in + (size_t)warp * 128 + 4 * lane);
    float s  = v.x + v.y + v.z + v.w;
    float sq = v.x * v.x + v.y * v.y + v.z * v.z + v.w * v.w;
#pragma unroll
    for (int o = 16; o; o >>= 1) {
        s  += __shfl_xor_sync(0xffffffffu, s,  o);
        sq += __shfl_xor_sync(0xffffffffu, sq, o);
    }
    float mu   = s * (1.f / 128.f);
    float rstd = rsqrtf(sq * (1.f / 128.f) - mu * mu + 1e-5f);
    float4 wv = *(const float4*)(w + 4 * lane);
    float4 bv = *(const float4*)(b + 4 * lane);
    float4 o4;
    o4.x = (v.x - mu) * rstd * wv.x + bv.x;
    o4.y = (v.y - mu) * rstd * wv.y + bv.y;
    o4.z = (v.z - mu) * rstd * wv.z + bv.z;
    o4.w = (v.w - mu) * rstd * wv.w + bv.w;
    *(float4*)(out + (size_t)warp * 128 + 4 * lane) = o4;
}

// ---------------- tensor-core GEMM body: tile 128x128, 3xTF32 mma.m16n8k8 -------------
// 8 warps = 4(m) x 2(n); warp tile 32x64; per warp 2 m-frags x 8 n-frags.
// A_sh [128][36] fp32 (split on the fly); Whi/Wlo [32][136] tf32-as-fp32.
// EPI: 0 none, 1 += bias[c]+res, 2 SiLU, 3 += res
#define AS 36
#define WS 136
template <int EPI>
__device__ __forceinline__ void gemm_body(
    const float* __restrict__ A, const float* __restrict__ W,
    const float* __restrict__ bias, const float* __restrict__ res,
    float* __restrict__ C, int M, int K, int NC, int row0, int cb,
    float* A_sh, float* Whi, float* Wlo) {
    int tid = threadIdx.x;
    int lane = tid & 31, wid = tid >> 5;
    int wm = wid >> 1, wn = wid & 1;
    int g = lane >> 2, t = lane & 3;
    float acc[2][8][4];
#pragma unroll
    for (int mf = 0; mf < 2; mf++)
#pragma unroll
        for (int nf = 0; nf < 8; nf++)
#pragma unroll
            for (int u = 0; u < 4; u++) acc[mf][nf][u] = 0.f;

    int nkt = K >> 5;
    for (int kt = 0; kt < nkt; ++kt) {
#pragma unroll
        for (int it = 0; it < 4; ++it) {   // A chunk 128x32
            int idx = tid + it * 256;
            int r = idx >> 3, c4 = (idx & 7) << 2;
            float4 v = make_float4(0.f, 0.f, 0.f, 0.f);
            if (row0 + r < M) v = *(const float4*)(A + (size_t)(row0 + r) * K + kt * 32 + c4);
            *(float4*)(A_sh + r * AS + c4) = v;
        }
#pragma unroll
        for (int it = 0; it < 4; ++it) {   // W chunk 32x128 -> hi/lo
            int idx = tid + it * 256;
            int kk = idx >> 5, wc = (idx & 31) << 2;
            float4 v = *(const float4*)(W + (size_t)(kt * 32 + kk) * NC + cb + wc);
            uint32_t h, l; float4 hv, lv;
            tf32split(v.x, h, l); hv.x = __uint_as_float(h); lv.x = __uint_as_float(l);
            tf32split(v.y, h, l); hv.y = __uint_as_float(h); lv.y = __uint_as_float(l);
            tf32split(v.z, h, l); hv.z = __uint_as_float(h); lv.z = __uint_as_float(l);
            tf32split(v.w, h, l); hv.w = __uint_as_float(h); lv.w = __uint_as_float(l);
            *(float4*)(Whi + kk * WS + wc) = hv;
            *(float4*)(Wlo + kk * WS + wc) = lv;
        }
        __syncthreads();
#pragma unroll
        for (int k8 = 0; k8 < 4; ++k8) {
            int ck = k8 * 8;
            uint32_t ahi[2][4], alo[2][4];
#pragma unroll
            for (int mf = 0; mf < 2; ++mf) {
                int rb = 32 * wm + 16 * mf;
                float a0 = A_sh[(rb + g)     * AS + ck + t];
                float a1 = A_sh[(rb + g + 8) * AS + ck + t];
                float a2 = A_sh[(rb + g)     * AS + ck + t + 4];
                float a3 = A_sh[(rb + g + 8) * AS + ck + t + 4];
                tf32split(a0, ahi[mf][0], alo[mf][0]);
                tf32split(a1, ahi[mf][1], alo[mf][1]);
                tf32split(a2, ahi[mf][2], alo[mf][2]);
                tf32split(a3, ahi[mf][3], alo[mf][3]);
            }
#pragma unroll
            for (int nf = 0; nf < 8; ++nf) {
                int nb = 64 * wn + 8 * nf + g;
                uint32_t bh0 = __float_as_uint(Whi[(ck + t)     * WS + nb]);
                uint32_t bh1 = __float_as_uint(Whi[(ck + t + 4) * WS + nb]);
                uint32_t bl0 = __float_as_uint(Wlo[(ck + t)     * WS + nb]);
                uint32_t bl1 = __float_as_uint(Wlo[(ck + t + 4) * WS + nb]);
#pragma unroll
                for (int mf = 0; mf < 2; ++mf) {
                    mma8(acc[mf][nf], alo[mf], bh0, bh1);
                    mma8(acc[mf][nf], ahi[mf], bl0, bl1);
                    mma8(acc[mf][nf], ahi[mf], bh0, bh1);
                }
            }
        }
        __syncthreads();
    }
    // epilogue: per (mf,nf): rows r0, r0+8; cols c, c+1 (float2)
#pragma unroll
    for (int mf = 0; mf < 2; ++mf) {
#pragma unroll
        for (int nf = 0; nf < 8; ++nf) {
            int c  = cb + 64 * wn + 8 * nf + 2 * t;
            int r0 = row0 + 32 * wm + 16 * mf + g;
            float2 v0 = make_float2(acc[mf][nf][0], acc[mf][nf][1]);
            float2 v1 = make_float2(acc[mf][nf][2], acc[mf][nf][3]);
            if (EPI == 2) {
                v0.x = v0.x / (1.f + expf(-v0.x)); v0.y = v0.y / (1.f + expf(-v0.y));
                v1.x = v1.x / (1.f + expf(-v1.x)); v1.y = v1.y / (1.f + expf(-v1.y));
            }
            if (r0 < M) {
                if (EPI == 1) {
                    float2 b = *(const float2*)(bias + c);
                    float2 rr = *(const float2*)(res + (size_t)r0 * NC + c);
                    v0.x += b.x + rr.x; v0.y += b.y + rr.y;
                }
                if (EPI == 3) {
                    float2 rr = *(const float2*)(res + (size_t)r0 * NC + c);
                    v0.x += rr.x; v0.y += rr.y;
                }
                *(float2*)(C + (size_t)r0 * NC + c) = v0;
            }
            int r1 = r0 + 8;
            if (r1 < M) {
                if (EPI == 1) {
                    float2 b = *(const float2*)(bias + c);
                    float2 rr = *(const float2*)(res + (size_t)r1 * NC + c);
                    v1.x += b.x + rr.x; v1.y += b.y + rr.y;
                }
                if (EPI == 3) {
                    float2 rr = *(const float2*)(res + (size_t)r1 * NC + c);
                    v1.x += rr.x; v1.y += rr.y;
                }
                *(float2*)(C + (size_t)r1 * NC + c) = v1;
            }
        }
    }
}

#define GEMM_SMEM ((128 * AS + 2 * 32 * WS) * 4)

template <int EPI>
__global__ void __launch_bounds__(256, 2) gemm_kernel(
    const float* __restrict__ A, const float* __restrict__ W,
    const float* __restrict__ bias, const float* __restrict__ res,
    float* __restrict__ C, int M, int K, int NC) {
    extern __shared__ float gsh[];
    float* A_sh = gsh;
    float* Whi  = gsh + 128 * AS;
    float* Wlo  = Whi + 32 * WS;
    gemm_body<EPI>(A, W, bias, res, C, M, K, NC, blockIdx.x * 128, blockIdx.y * 128,
                   A_sh, Whi, Wlo);
}

// fused Q/K/V: grid.y selects the weight + output
__global__ void __launch_bounds__(256, 2) qkv_kernel(
    const float* __restrict__ A,
    const float* __restrict__ Wq, const float* __restrict__ Wk, const float* __restrict__ Wv,
    float* __restrict__ Q, float* __restrict__ Ko, float* __restrict__ V, int M) {
    extern __shared__ float gsh[];
    float* A_sh = gsh;
    float* Whi  = gsh + 128 * AS;
    float* Wlo  = Whi + 32 * WS;
    const float* W = (blockIdx.y == 0) ? Wq : (blockIdx.y == 1) ? Wk : Wv;
    float* C       = (blockIdx.y == 0) ? Q  : (blockIdx.y == 1) ? Ko : V;
    gemm_body<0>(A, W, nullptr, nullptr, C, M, 128, 128, blockIdx.x * 128, 0, A_sh, Whi, Wlo);
}

// ---------------- fused edge kernel: LN -> Pe GEMM (3xTF32) -> score/exp -> scatter ----
// LN_sh [128][132] fp32 (A operand, split on the fly); Pe overwrites it after GEMM.
#define LN_STRIDE 132
__global__ void __launch_bounds__(256, 2) edge_kernel(
    const float* __restrict__ ef, const float* __restrict__ lnw, const float* __restrict__ lnb,
    const float* __restrict__ We, const int* __restrict__ src, const int* __restrict__ dst,
    const float* __restrict__ Q, const float* __restrict__ Kv, const float* __restrict__ V,
    float* __restrict__ wV, float* __restrict__ z, int E) {
    extern __shared__ float sh[];
    float* LN_sh = sh;                           // [128][132]
    float* Whi   = sh + 128 * LN_STRIDE;         // [32][136]
    float* Wlo   = Whi + 32 * WS;                // [32][136]
    int* s_sh = (int*)(Wlo + 32 * WS);           // [128]
    int* d_sh = s_sh + 128;                      // [128]

    int tid = threadIdx.x, lane = tid & 31, w = tid >> 5;
    int e0 = blockIdx.x * 128;
    if (tid < 128) {
        int e = e0 + tid;
        s_sh[tid] = (e < E) ? src[e] : 0;
        d_sh[tid] = (e < E) ? dst[e] : 0;
    }
    float4 lw = *(const float4*)(lnw + 4 * lane);
    float4 lb = *(const float4*)(lnb + 4 * lane);
    // phase A: LN of 16 edge rows per warp
#pragma unroll
    for (int i = 0; i < 16; i++) {
        int r = w * 16 + i;
        int e = e0 + r;
        float4 v = make_float4(0.f, 0.f, 0.f, 0.f);
        if (e < E) v = *(const float4*)(ef + (size_t)e * 128 + 4 * lane);
        float s  = v.x + v.y + v.z + v.w;
        float sq = v.x * v.x + v.y * v.y + v.z * v.z + v.w * v.w;
#pragma unroll
        for (int o = 16; o; o >>= 1) {
            s  += __shfl_xor_sync(0xffffffffu, s,  o);
            sq += __shfl_xor_sync(0xffffffffu, sq, o);
        }
        float mu   = s * (1.f / 128.f);
        float rstd = rsqrtf(sq * (1.f / 128.f) - mu * mu + 1e-5f);
        float4 o4;
        o4.x = (v.x - mu) * rstd * lw.x + lb.x;
        o4.y = (v.y - mu) * rstd * lw.y + lb.y;
        o4.z = (v.z - mu) * rstd * lw.z + lb.z;
        o4.w = (v.w - mu) * rstd * lw.w + lb.w;
        *(float4*)(LN_sh + r * LN_STRIDE + 4 * lane) = o4;
    }
    __syncthreads();
    // phase B: Pe[128][128] = LN @ We via 3xTF32 mma
    int wm = w >> 1, wn = w & 1;
    int g = lane >> 2, t = lane & 3;
    float acc[2][8][4];
#pragma unroll
    for (int mf = 0; mf < 2; mf++)
#pragma unroll
        for (int nf = 0; nf < 8; nf++)
#pragma unroll
            for (int u = 0; u < 4; u++) acc[mf][nf][u] = 0.f;
    for (int kt = 0; kt < 4; ++kt) {
#pragma unroll
        for (int it = 0; it < 4; ++it) {
            int idx = tid + it * 256;
            int kk = idx >> 5, wc = (idx & 31) << 2;
            float4 v = *(const float4*)(We + (size_t)(kt * 32 + kk) * 128 + wc);
            uint32_t h, l; float4 hv, lv;
            tf32split(v.x, h, l); hv.x = __uint_as_float(h); lv.x = __uint_as_float(l);
            tf32split(v.y, h, l); hv.y = __uint_as_float(h); lv.y = __uint_as_float(l);
            tf32split(v.z, h, l); hv.z = __uint_as_float(h); lv.z = __uint_as_float(l);
            tf32split(v.w, h, l); hv.w = __uint_as_float(h); lv.w = __uint_as_float(l);
            *(float4*)(Whi + kk * WS + wc) = hv;
            *(float4*)(Wlo + kk * WS + wc) = lv;
        }
        __syncthreads();
#pragma unroll
        for (int k8 = 0; k8 < 4; ++k8) {
            int ckA = kt * 32 + k8 * 8;   // col in LN (full K)
            int ckW = k8 * 8;             // row in W chunk
            uint32_t ahi[2][4], alo[2][4];
#pragma unroll
            for (int mf = 0; mf < 2; ++mf) {
                int rb = 32 * wm + 16 * mf;
                float a0 = LN_sh[(rb + g)     * LN_STRIDE + ckA + t];
                float a1 = LN_sh[(rb + g + 8) * LN_STRIDE + ckA + t];
                float a2 = LN_sh[(rb + g)     * LN_STRIDE + ckA + t + 4];
                float a3 = LN_sh[(rb + g + 8) * LN_STRIDE + ckA + t + 4];
                tf32split(a0, ahi[mf][0], alo[mf][0]);
                tf32split(a1, ahi[mf][1], alo[mf][1]);
                tf32split(a2, ahi[mf][2], alo[mf][2]);
                tf32split(a3, ahi[mf][3], alo[mf][3]);
            }
#pragma unroll
            for (int nf = 0; nf < 8; ++nf) {
                int nb = 64 * wn + 8 * nf + g;
                uint32_t bh0 = __float_as_uint(Whi[(ckW + t)     * WS + nb]);
                uint32_t bh1 = __float_as_uint(Whi[(ckW + t + 4) * WS + nb]);
                uint32_t bl0 = __float_as_uint(Wlo[(ckW + t)     * WS + nb]);
                uint32_t bl1 = __float_as_uint(Wlo[(ckW + t + 4) * WS + nb]);
#pragma unroll
                for (int mf = 0; mf < 2; ++mf) {
                    mma8(acc[mf][nf], alo[mf], bh0, bh1);
                    mma8(acc[mf][nf], ahi[mf], bl0, bl1);
                    mma8(acc[mf][nf], ahi[mf], bh0, bh1);
                }
            }
        }
        __syncthreads();
    }
    // stash Pe into LN_sh (LN values dead; all MMAs done at this point)
#pragma unroll
    for (int mf = 0; mf < 2; ++mf) {
#pragma unroll
        for (int nf = 0; nf < 8; ++nf) {
            int r0 = 32 * wm + 16 * mf + g;
            int c  = 64 * wn + 8 * nf + 2 * t;
            *(float2*)(LN_sh + r0 * LN_STRIDE + c)       = make_float2(acc[mf][nf][0], acc[mf][nf][1]);
            *(float2*)(LN_sh + (r0 + 8) * LN_STRIDE + c) = make_float2(acc[mf][nf][2], acc[mf][nf][3]);
        }
    }
    __syncthreads();
    // phase C: per-edge score, exp, scatter (16 edges per warp, prefetched)
    const float inv = 0.17677669529663687f;  // 1/sqrt(32)
    int head = lane >> 3;
    int base = w * 16;
    int si = s_sh[base], di = d_sh[base];
    float4 kq = *(const float4*)(Kv + (size_t)si * 128 + 4 * lane);
    float4 qv = *(const float4*)(Q  + (size_t)di * 128 + 4 * lane);
    float4 vv = *(const float4*)(V  + (size_t)si * 128 + 4 * lane);
#pragma unroll
    for (int j = 0; j < 16; j++) {
        int e = e0 + base + j;
        float4 kqc = kq, qvc = qv, vvc = vv;
        int dic = di;
        if (j < 15) {
            int sn = s_sh[base + j + 1], dn = d_sh[base + j + 1];
            kq = *(const float4*)(Kv + (size_t)sn * 128 + 4 * lane);
            qv = *(const float4*)(Q  + (size_t)dn * 128 + 4 * lane);
            vv = *(const float4*)(V  + (size_t)sn * 128 + 4 * lane);
            di = dn;
        }
        if (e < E) {
            float4 pe = *(float4*)(LN_sh + (base + j) * LN_STRIDE + 4 * lane);
            float tt = clip5(kqc.x * qvc.x * inv) * pe.x + clip5(kqc.y * qvc.y * inv) * pe.y
                     + clip5(kqc.z * qvc.z * inv) * pe.z + clip5(kqc.w * qvc.w * inv) * pe.w;
            tt += __shfl_xor_sync(0xffffffffu, tt, 1);
            tt += __shfl_xor_sync(0xffffffffu, tt, 2);
            tt += __shfl_xor_sync(0xffffffffu, tt, 4);
            float s = expf(clip5(tt));
            float* dp = wV + (size_t)dic * 128 + 4 * lane;
            red_add_v4(dp, vvc.x * s, vvc.y * s, vvc.z * s, vvc.w * s);
            if ((lane & 7) == 0) red_add_f(z + (size_t)dic * 4 + head, s);
        }
    }
}
#define EDGE_SMEM ((128 * LN_STRIDE + 2 * 32 * WS) * 4 + 2 * 128 * 4)

// ---------------- attn = wV / (z + 1e-6) ----------------
__global__ void attn_kernel(const float* __restrict__ wV, const float* __restrict__ z,
                            float* __restrict__ outp, int N) {
    int i = blockIdx.x * blockDim.x + threadIdx.x;  // over N*32 float4s
    if (i >= N * 32) return;
    int n = i >> 5;
    int head = (i & 31) >> 3;
    float invz = 1.f / (z[(size_t)n * 4 + head] + 1e-6f);
    float4 v = *(const float4*)(wV + (size_t)i * 4);
    v.x *= invz; v.y *= invz; v.z *= invz; v.w *= invz;
    *(float4*)(outp + (size_t)i * 4) = v;
}

// ---------------- Set2Set: one block per graph, all 3 iterations internal ----------------
__global__ void __launch_bounds__(256) set2set_kernel(
    const float* __restrict__ nf, const int* __restrict__ gid,
    const float* __restrict__ W_ih, const float* __restrict__ W_hh,
    const float* __restrict__ b_ih, const float* __restrict__ b_hh,
    float* __restrict__ ener, float* __restrict__ out, int N) {
    __shared__ float qs[256], hh[128], cc[128], gates[512], rsh[8 * 128], red[16];
    int tid = threadIdx.x, lane = tid & 31, w = tid >> 5;
    int g = blockIdx.x;
    int lo, hi;
    {
        int a = 0, b = N;
        while (a < b) { int m = (a + b) >> 1; if (gid[m] < g) a = m + 1; else b = m; }
        lo = a;
        b = N;
        while (a < b) { int m = (a + b) >> 1; if (gid[m] < g + 1) a = m + 1; else b = m; }
        hi = a;
    }
    qs[tid] = 0.f;
    if (tid < 128) { hh[tid] = 0.f; cc[tid] = 0.f; }
    __syncthreads();

    for (int it = 0; it < 3; ++it) {
        for (int j = tid; j < 512; j += 256) {
            float acc = b_ih[j] + b_hh[j];
            const float* wi = W_ih + (size_t)j * 256;
#pragma unroll 8
            for (int k2 = 0; k2 < 256; k2++) acc += qs[k2] * wi[k2];
            const float* whp = W_hh + (size_t)j * 128;
#pragma unroll 8
            for (int k2 = 0; k2 < 128; k2++) acc += hh[k2] * whp[k2];
            gates[j] = acc;
        }
        __syncthreads();
        if (tid < 128) {
            float c = sigm(gates[128 + tid]) * cc[tid] + sigm(gates[tid]) * tanhf(gates[256 + tid]);
            cc[tid] = c;
            hh[tid] = sigm(gates[384 + tid]) * tanhf(c);
        }
        __syncthreads();
        float mloc = -INFINITY;
        float4 h4 = *(float4*)&hh[4 * lane];
        for (int n = lo + w; n < hi; n += 8) {
            float4 a4 = *(const float4*)(nf + (size_t)n * 128 + 4 * lane);
            float t = a4.x * h4.x + a4.y * h4.y + a4.z * h4.z + a4.w * h4.w;
#pragma unroll
            for (int o = 16; o; o >>= 1) t += __shfl_xor_sync(0xffffffffu, t, o);
            if (lane == 0) ener[n] = t;
            mloc = fmaxf(mloc, t);
        }
#pragma unroll
        for (int o = 16; o; o >>= 1) mloc = fmaxf(mloc, __shfl_xor_sync(0xffffffffu, mloc, o));
        if (lane == 0) red[w] = mloc;
        __syncthreads();
        if (tid == 0) {
            float m = -INFINITY;
            for (int i = 0; i < 8; i++) m = fmaxf(m, red[i]);
            red[8] = m;
        }
        __syncthreads();
        float m = red[8];
        float dloc = 0.f;
        for (int n = lo + tid; n < hi; n += 256) dloc += expf(ener[n] - m);
#pragma unroll
        for (int o = 16; o; o >>= 1) dloc += __shfl_xor_sync(0xffffffffu, dloc, o);
        __syncthreads();
        if (lane == 0) red[w] = dloc;
        __syncthreads();
        if (tid == 0) {
            float d = 0.f;
            for (int i = 0; i < 8; i++) d += red[i];
            red[9] = d;
        }
        __syncthreads();
        float invd = 1.f / red[9];
        float4 racc = make_float4(0.f, 0.f, 0.f, 0.f);
        for (int n = lo + w; n < hi; n += 8) {
            float coef = expf(ener[n] - m) * invd;
            float4 a4 = *(const float4*)(nf + (size_t)n * 128 + 4 * lane);
            racc.x += coef * a4.x; racc.y += coef * a4.y;
            racc.z += coef * a4.z; racc.w += coef * a4.w;
        }
        *(float4*)&rsh[w * 128 + 4 * lane] = racc;
        __syncthreads();
        if (tid < 128) {
            float ro = 0.f;
#pragma unroll
            for (int i = 0; i < 8; i++) ro += rsh[i * 128 + tid];
            qs[tid] = hh[tid];
            qs[128 + tid] = ro;
        }
        __syncthreads();
    }
    out[(size_t)g * 256 + tid] = qs[tid];
}

// ---------------- launch ----------------
extern "C" void kernel_launch(void* const* d_in, const int* in_sizes, int n_in,
                              void* d_out, int out_size) {
    const float* node = (const float*)d_in[0];
    const float* edge = (const float*)d_in[1];
    const float* Wq = (const float*)d_in[2];
    const float* Wk = (const float*)d_in[3];
    const float* Wv = (const float*)d_in[4];
    const float* We = (const float*)d_in[5];
    const float* Wo = (const float*)d_in[6];
    const float* bo = (const float*)d_in[7];
    const float* W1 = (const float*)d_in[8];
    const float* W2 = (const float*)d_in[9];
    const float* l1nw = (const float*)d_in[10];
    const float* l1nb = (const float*)d_in[11];
    const float* l1ew = (const float*)d_in[12];
    const float* l1eb = (const float*)d_in[13];
    const float* l2w = (const float*)d_in[14];
    const float* l2b = (const float*)d_in[15];
    const float* Wih = (const float*)d_in[16];
    const float* Whh = (const float*)d_in[17];
    const float* bih = (const float*)d_in[18];
    const float* bhh = (const float*)d_in[19];
    const int* src = (const int*)d_in[20];
    const int* dst = (const int*)d_in[21];
    const int* gid = (const int*)d_in[22];

    int N = in_sizes[0] / 128;
    int E = in_sizes[20];
    int G = out_size / 256;

    float *b1, *q, *k, *v, *x, *wv, *z, *t, *en;
    cudaGetSymbolAddress((void**)&b1, g_b1);
    cudaGetSymbolAddress((void**)&q,  g_Q);
    cudaGetSymbolAddress((void**)&k,  g_K);
    cudaGetSymbolAddress((void**)&v,  g_V);
    cudaGetSymbolAddress((void**)&x,  g_x);
    cudaGetSymbolAddress((void**)&wv, g_wV);
    cudaGetSymbolAddress((void**)&z,  g_z);
    cudaGetSymbolAddress((void**)&t,  g_t);
    cudaGetSymbolAddress((void**)&en, g_en);

    cudaFuncSetAttribute(edge_kernel, cudaFuncAttributeMaxDynamicSharedMemorySize, EDGE_SMEM);
    cudaFuncSetAttribute(qkv_kernel, cudaFuncAttributeMaxDynamicSharedMemorySize, GEMM_SMEM);
    cudaFuncSetAttribute(gemm_kernel<1>, cudaFuncAttributeMaxDynamicSharedMemorySize, GEMM_SMEM);
    cudaFuncSetAttribute(gemm_kernel<2>, cudaFuncAttributeMaxDynamicSharedMemorySize, GEMM_SMEM);
    cudaFuncSetAttribute(gemm_kernel<3>, cudaFuncAttributeMaxDynamicSharedMemorySize, GEMM_SMEM);

    int gnodes = (N + 127) / 128;

    // 1) LN(node) -> b1
    ln_kernel<<<(N + 7) / 8, 256>>>(node, b1, l1nw, l1nb, N);
    // 2) Q, K, V (single fused launch)
    qkv_kernel<<<dim3(gnodes, 3), 256, GEMM_SMEM>>>(b1, Wq, Wk, Wv, q, k, v, N);
    // 3) zero accumulators
    fzero_kernel<<<(N * 32 + 255) / 256, 256>>>((float4*)wv, N * 32);
    fzero_kernel<<<(N + 255) / 256, 256>>>((float4*)z, N);
    // 4) fused edge kernel (128-edge tiles)
    edge_kernel<<<(E + 127) / 128, 256, EDGE_SMEM>>>(edge, l1ew, l1eb, We, src, dst,
                                                     q, k, v, wv, z, E);
    // 5) attn -> b1
    attn_kernel<<<(N * 32 + 255) / 256, 256>>>(wv, z, b1, N);
    // 6) x = node + attn@Wo + bo
    gemm_kernel<1><<<dim3(gnodes, 1), 256, GEMM_SMEM>>>(b1, Wo, bo, node, x, N, 128, 128);
    // 7) y = LN2(x) -> q (reuse)
    ln_kernel<<<(N + 7) / 8, 256>>>(x, q, l2w, l2b, N);
    // 8) t = silu(y @ W1)   [N,256]
    gemm_kernel<2><<<dim3(gnodes, 2), 256, GEMM_SMEM>>>(q, W1, nullptr, nullptr, t, N, 128, 256);
    // 9) nf = x + t @ W2 -> k (reuse)
    gemm_kernel<3><<<dim3(gnodes, 1), 256, GEMM_SMEM>>>(t, W2, nullptr, x, k, N, 256, 128);
    // 10) Set2Set readout (3 iterations inside)
    set2set_kernel<<<G, 256>>>(k, gid, Wih, Whh, bih, bhh, en, (float*)d_out, N);
}